// round 2
// baseline (speedup 1.0000x reference)
#include <cuda_runtime.h>
#include <cuda_bf16.h>
#include <cstdint>

// Problem constants (fixed by the reference: N=4, T=1024, H=16, D_HEAD=64)
#define T_LEN 1024
#define HEADS 16
#define DH 64
#define NB_MAX 4

// Scratch (device globals — no allocation allowed in kernel_launch)
__device__ float g_q[NB_MAX * HEADS * T_LEN * DH];   // [bh][t][d]
__device__ float g_k[NB_MAX * HEADS * T_LEN * DH];
__device__ float g_v[NB_MAX * HEADS * T_LEN * DH];
__device__ float g_R[(size_t)NB_MAX * HEADS * T_LEN * T_LEN]; // [bh][t][c], c = s-t+1023

// ---------------------------------------------------------------------------
// Projection: out = x @ W + b, scattered to [b,h,t,d] layout.
// 128x128 tile, BK=16, 256 threads, 8x8 microtile. gridDim.z selects q/k/v.
// ---------------------------------------------------------------------------
__global__ __launch_bounds__(256) void proj_kernel(
    const float* __restrict__ x,
    const float* __restrict__ Wq, const float* __restrict__ bq,
    const float* __restrict__ Wk, const float* __restrict__ bk,
    const float* __restrict__ Wv, const float* __restrict__ bv)
{
    const float* W; const float* bias; float* outp;
    if (blockIdx.z == 0)      { W = Wq; bias = bq; outp = g_q; }
    else if (blockIdx.z == 1) { W = Wk; bias = bk; outp = g_k; }
    else                      { W = Wv; bias = bv; outp = g_v; }

    __shared__ float As[16][132];   // transposed A tile, padded
    __shared__ float Bs[16][128];

    int tid = threadIdx.x;
    int tx = tid & 15, ty = tid >> 4;
    int m0 = blockIdx.y * 128;
    int n0 = blockIdx.x * 128;

    float acc[8][8];
    #pragma unroll
    for (int i = 0; i < 8; i++)
        #pragma unroll
        for (int j = 0; j < 8; j++) acc[i][j] = 0.f;

    for (int k0 = 0; k0 < 1024; k0 += 16) {
        // Load A (128x16) transposed into As
        #pragma unroll
        for (int i = tid; i < 512; i += 256) {
            int r = i >> 2, c = (i & 3) << 2;
            float4 a = *(const float4*)&x[(size_t)(m0 + r) * 1024 + k0 + c];
            As[c + 0][r] = a.x; As[c + 1][r] = a.y;
            As[c + 2][r] = a.z; As[c + 3][r] = a.w;
        }
        // Load B (16x128) natural
        #pragma unroll
        for (int i = tid; i < 512; i += 256) {
            int r = i >> 5, c = (i & 31) << 2;
            *(float4*)&Bs[r][c] = *(const float4*)&W[(size_t)(k0 + r) * 1024 + n0 + c];
        }
        __syncthreads();
        #pragma unroll
        for (int kk = 0; kk < 16; kk++) {
            float a[8], b[8];
            *(float4*)(a)     = *(const float4*)&As[kk][ty * 8];
            *(float4*)(a + 4) = *(const float4*)&As[kk][ty * 8 + 4];
            *(float4*)(b)     = *(const float4*)&Bs[kk][tx * 8];
            *(float4*)(b + 4) = *(const float4*)&Bs[kk][tx * 8 + 4];
            #pragma unroll
            for (int i = 0; i < 8; i++)
                #pragma unroll
                for (int j = 0; j < 8; j++)
                    acc[i][j] += a[i] * b[j];
        }
        __syncthreads();
    }

    // Epilogue: bias + scatter to [b,h,t,d]
    #pragma unroll
    for (int i = 0; i < 8; i++) {
        int m = m0 + ty * 8 + i;
        int b = m >> 10, t = m & 1023;
        #pragma unroll
        for (int j = 0; j < 8; j++) {
            int n = n0 + tx * 8 + j;
            int h = n >> 6, d = n & 63;
            outp[(((size_t)b * HEADS + h) * T_LEN + t) * DH + d] = acc[i][j] + bias[n];
        }
    }
}

// ---------------------------------------------------------------------------
// Relative scores: R[bh][t][c] = q[bh][t] . Er[c]
// 64x64 tile per block, K=64. Skip tiles entirely below the needed band
// (only c + t >= 1023 is ever read by the causal attention).
// ---------------------------------------------------------------------------
__global__ __launch_bounds__(256) void rel_kernel(const float* __restrict__ Er)
{
    int sb = blockIdx.x, tb = blockIdx.y, bh = blockIdx.z;
    if (tb + sb < 15) return;   // tile never read under causal mask

    __shared__ float qs[64][68];   // qs[t][d]
    __shared__ float es[64][68];   // es[d][c]  (Er transposed)

    int t0 = tb * 64, s0 = sb * 64;
    const float* qg = g_q + (size_t)bh * T_LEN * DH;

    int tid = threadIdx.x;
    int tx = tid & 15, ty = tid >> 4;
    int r4 = ty * 4, c4 = tx * 4;

    for (int idx = tid; idx < 4096; idx += 256) {
        int r = idx >> 6, c = idx & 63;
        qs[r][c] = qg[(t0 + r) * DH + c];
        es[c][r] = Er[(s0 + r) * DH + c];
    }
    __syncthreads();

    float acc[4][4];
    #pragma unroll
    for (int i = 0; i < 4; i++)
        #pragma unroll
        for (int j = 0; j < 4; j++) acc[i][j] = 0.f;

    #pragma unroll 16
    for (int d = 0; d < 64; d++) {
        float4 b4 = *(const float4*)&es[d][c4];
        #pragma unroll
        for (int i = 0; i < 4; i++) {
            float a = qs[r4 + i][d];
            acc[i][0] += a * b4.x; acc[i][1] += a * b4.y;
            acc[i][2] += a * b4.z; acc[i][3] += a * b4.w;
        }
    }

    float* Rg = g_R + (size_t)bh * T_LEN * T_LEN;
    #pragma unroll
    for (int i = 0; i < 4; i++) {
        *(float4*)&Rg[(size_t)(t0 + r4 + i) * T_LEN + s0 + c4] =
            make_float4(acc[i][0], acc[i][1], acc[i][2], acc[i][3]);
    }
}

// ---------------------------------------------------------------------------
// Flash attention with relative-position gather.
// One block = (bh, 64-row t-tile). Online softmax, 4x4 microtiles, 256 thr.
// ---------------------------------------------------------------------------
#define AT_SMEM_BYTES (3 * 64 * 68 * 4)

__global__ __launch_bounds__(256) void attn_kernel(float* __restrict__ out)
{
    extern __shared__ float sm[];
    float (*q_s)[68]  = (float(*)[68])(sm);
    float (*kv_s)[68] = (float(*)[68])(sm + 64 * 68);
    float (*p_s)[68]  = (float(*)[68])(sm + 2 * 64 * 68);

    int tb = blockIdx.x;
    int bh = blockIdx.y;
    int t0 = tb * 64;

    const float* qg = g_q + (size_t)bh * T_LEN * DH;
    const float* kg = g_k + (size_t)bh * T_LEN * DH;
    const float* vg = g_v + (size_t)bh * T_LEN * DH;
    const float* Rg = g_R + (size_t)bh * T_LEN * T_LEN;

    int tid = threadIdx.x;
    int tx = tid & 15, ty = tid >> 4;
    int r4 = ty * 4, c4 = tx * 4;

    // load q tile (natural layout)
    for (int idx = tid; idx < 4096; idx += 256) {
        int r = idx >> 6, c = idx & 63;
        q_s[r][c] = qg[(t0 + r) * DH + c];
    }

    float m_i[4], l_i[4], o_acc[4][4];
    #pragma unroll
    for (int i = 0; i < 4; i++) {
        m_i[i] = -1e30f; l_i[i] = 0.f;
        #pragma unroll
        for (int j = 0; j < 4; j++) o_acc[i][j] = 0.f;
    }

    for (int sb = 0; sb <= tb; sb++) {
        int s0 = sb * 64;
        __syncthreads();   // protects q load (iter 0) and p_s/kv_s reads (iter>0)
        // load k transposed: kv_s[d][j]
        for (int idx = tid; idx < 4096; idx += 256) {
            int j = idx >> 6, d = idx & 63;
            kv_s[d][j] = kg[(s0 + j) * DH + d];
        }
        __syncthreads();

        // S = q @ k^T (64x64, each thread 4x4)
        float s_t[4][4];
        #pragma unroll
        for (int i = 0; i < 4; i++)
            #pragma unroll
            for (int j = 0; j < 4; j++) s_t[i][j] = 0.f;

        #pragma unroll 16
        for (int d = 0; d < 64; d++) {
            float4 b4 = *(const float4*)&kv_s[d][c4];
            #pragma unroll
            for (int i = 0; i < 4; i++) {
                float a = q_s[r4 + i][d];
                s_t[i][0] += a * b4.x; s_t[i][1] += a * b4.y;
                s_t[i][2] += a * b4.z; s_t[i][3] += a * b4.w;
            }
        }

        // add relative term, scale, causal mask
        #pragma unroll
        for (int i = 0; i < 4; i++) {
            int t = t0 + r4 + i;
            const float* Rrow = Rg + (size_t)t * T_LEN + (T_LEN - 1 - t);
            #pragma unroll
            for (int j = 0; j < 4; j++) {
                int s = s0 + c4 + j;
                if (s <= t)
                    s_t[i][j] = (s_t[i][j] + Rrow[s]) * 0.125f;  // 1/sqrt(64)
                else
                    s_t[i][j] = -1e30f;
            }
        }

        // online softmax update
        #pragma unroll
        for (int i = 0; i < 4; i++) {
            float mx = fmaxf(fmaxf(s_t[i][0], s_t[i][1]), fmaxf(s_t[i][2], s_t[i][3]));
            #pragma unroll
            for (int off = 8; off >= 1; off >>= 1)
                mx = fmaxf(mx, __shfl_xor_sync(0xffffffffu, mx, off));
            float mn = fmaxf(m_i[i], mx);
            float alpha = __expf(m_i[i] - mn);
            m_i[i] = mn;
            float rs = 0.f;
            #pragma unroll
            for (int j = 0; j < 4; j++) {
                float p = __expf(s_t[i][j] - mn);
                s_t[i][j] = p; rs += p;
            }
            #pragma unroll
            for (int off = 8; off >= 1; off >>= 1)
                rs += __shfl_xor_sync(0xffffffffu, rs, off);
            l_i[i] = l_i[i] * alpha + rs;
            #pragma unroll
            for (int j = 0; j < 4; j++) o_acc[i][j] *= alpha;
        }

        // write P tile
        #pragma unroll
        for (int i = 0; i < 4; i++)
            *(float4*)&p_s[r4 + i][c4] =
                make_float4(s_t[i][0], s_t[i][1], s_t[i][2], s_t[i][3]);
        __syncthreads();

        // load v natural: kv_s[j][d]
        for (int idx = tid; idx < 4096; idx += 256) {
            int j = idx >> 6, d = idx & 63;
            kv_s[j][d] = vg[(s0 + j) * DH + d];
        }
        __syncthreads();

        // O += P @ V
        #pragma unroll 16
        for (int j = 0; j < 64; j++) {
            float4 v4 = *(const float4*)&kv_s[j][c4];
            #pragma unroll
            for (int i = 0; i < 4; i++) {
                float p = p_s[r4 + i][j];
                o_acc[i][0] += p * v4.x; o_acc[i][1] += p * v4.y;
                o_acc[i][2] += p * v4.z; o_acc[i][3] += p * v4.w;
            }
        }
    }

    // epilogue: out[b][t][h*64+d]
    int b = bh >> 4, h = bh & 15;
    #pragma unroll
    for (int i = 0; i < 4; i++) {
        int t = t0 + r4 + i;
        float inv = 1.f / l_i[i];
        float* op = out + ((size_t)b * T_LEN + t) * (HEADS * DH) + h * DH + c4;
        *(float4*)op = make_float4(o_acc[i][0] * inv, o_acc[i][1] * inv,
                                   o_acc[i][2] * inv, o_acc[i][3] * inv);
    }
}

// ---------------------------------------------------------------------------
extern "C" void kernel_launch(void* const* d_in, const int* in_sizes, int n_in,
                              void* d_out, int out_size)
{
    const float* x  = (const float*)d_in[0];
    const float* Wq = (const float*)d_in[1];
    const float* bq = (const float*)d_in[2];
    const float* Wk = (const float*)d_in[3];
    const float* bk = (const float*)d_in[4];
    const float* Wv = (const float*)d_in[5];
    const float* bv = (const float*)d_in[6];
    const float* Er = (const float*)d_in[7];
    float* out = (float*)d_out;

    int NB = in_sizes[0] / (T_LEN * 1024);  // batch (4)
    if (NB > NB_MAX) NB = NB_MAX;

    cudaFuncSetAttribute(attn_kernel,
                         cudaFuncAttributeMaxDynamicSharedMemorySize,
                         AT_SMEM_BYTES);

    // 1) q,k,v projections
    dim3 pgrid(8, NB * 8, 3);
    proj_kernel<<<pgrid, 256>>>(x, Wq, bq, Wk, bk, Wv, bv);

    // 2) relative scores R = q @ Er^T (upper band only)
    dim3 rgrid(16, 16, NB * HEADS);
    rel_kernel<<<rgrid, 256>>>(Er);

    // 3) flash attention + rel gather + output merge
    dim3 agrid(16, NB * HEADS);
    attn_kernel<<<agrid, 256, AT_SMEM_BYTES>>>(out);
}

// round 5
// speedup vs baseline: 1.2993x; 1.2993x over previous
#include <cuda_runtime.h>
#include <cuda_bf16.h>
#include <cstdint>

// Problem constants (fixed by the reference: N=4, T=1024, H=16, D_HEAD=64)
#define T_LEN 1024
#define HEADS 16
#define DH 64
#define NB_MAX 4
#define DM 1024

// ---------------------------------------------------------------------------
// Scratch (device globals — no allocation allowed in kernel_launch)
// ---------------------------------------------------------------------------
__device__ __align__(16) float g_q[NB_MAX * HEADS * T_LEN * DH];   // [bh][t][d]
__device__ __align__(16) float g_k[NB_MAX * HEADS * T_LEN * DH];
__device__ __align__(16) float g_v[NB_MAX * HEADS * T_LEN * DH];
__device__ __align__(16) float g_R[(size_t)NB_MAX * HEADS * T_LEN * T_LEN]; // [bh][t][c], c=s-t+1023
// bf16 hi/lo split operands for HMMA
__device__ __align__(16) __nv_bfloat16 g_xh[NB_MAX * T_LEN * DM];
__device__ __align__(16) __nv_bfloat16 g_xl[NB_MAX * T_LEN * DM];
__device__ __align__(16) __nv_bfloat16 g_wth[3 * DM * DM];  // W^T [mat][n][k]
__device__ __align__(16) __nv_bfloat16 g_wtl[3 * DM * DM];

// mma.sync m16n8k16 row.col f32.bf16.bf16.f32 (base PTX — works on sm_100)
#define MMA16816(d, a0, a1, a2, a3, b0, b1)                                   \
    asm volatile(                                                             \
        "mma.sync.aligned.m16n8k16.row.col.f32.bf16.bf16.f32 "                \
        "{%0,%1,%2,%3}, {%4,%5,%6,%7}, {%8,%9}, {%0,%1,%2,%3};"               \
        : "+f"((d)[0]), "+f"((d)[1]), "+f"((d)[2]), "+f"((d)[3])              \
        : "r"(a0), "r"(a1), "r"(a2), "r"(a3), "r"(b0), "r"(b1))

// ---------------------------------------------------------------------------
// prep_x: fp32 x -> bf16 hi/lo (same [m][k] layout)
// ---------------------------------------------------------------------------
__global__ __launch_bounds__(256) void prep_x(const float* __restrict__ x, int n4)
{
    int i = blockIdx.x * 256 + threadIdx.x;
    if (i >= n4) return;
    float4 v = ((const float4*)x)[i];
    __nv_bfloat16 h[4], l[4];
    float f[4] = {v.x, v.y, v.z, v.w};
    #pragma unroll
    for (int j = 0; j < 4; j++) {
        h[j] = __float2bfloat16(f[j]);
        l[j] = __float2bfloat16(f[j] - __bfloat162float(h[j]));
    }
    __nv_bfloat162* oh = (__nv_bfloat162*)g_xh;
    __nv_bfloat162* ol = (__nv_bfloat162*)g_xl;
    oh[2 * i]     = __halves2bfloat162(h[0], h[1]);
    oh[2 * i + 1] = __halves2bfloat162(h[2], h[3]);
    ol[2 * i]     = __halves2bfloat162(l[0], l[1]);
    ol[2 * i + 1] = __halves2bfloat162(l[2], l[3]);
}

// ---------------------------------------------------------------------------
// prep_w: transpose W [k][n] -> W^T [n][k], split to bf16 hi/lo
// ---------------------------------------------------------------------------
__global__ __launch_bounds__(256) void prep_w(const float* __restrict__ Wq,
                                              const float* __restrict__ Wk,
                                              const float* __restrict__ Wv)
{
    const float* W = (blockIdx.z == 0) ? Wq : (blockIdx.z == 1) ? Wk : Wv;
    __shared__ float t[32][33];
    int tx = threadIdx.x, ty = threadIdx.y;        // 32 x 8
    int n0 = blockIdx.x * 32, k0 = blockIdx.y * 32;
    #pragma unroll
    for (int i = 0; i < 4; i++)
        t[ty + 8 * i][tx] = W[(size_t)(k0 + ty + 8 * i) * DM + n0 + tx];
    __syncthreads();
    __nv_bfloat16* oh = g_wth + (size_t)blockIdx.z * DM * DM;
    __nv_bfloat16* ol = g_wtl + (size_t)blockIdx.z * DM * DM;
    #pragma unroll
    for (int i = 0; i < 4; i++) {
        int n = n0 + ty + 8 * i;
        float v = t[tx][ty + 8 * i];
        __nv_bfloat16 h = __float2bfloat16(v);
        oh[(size_t)n * DM + k0 + tx] = h;
        ol[(size_t)n * DM + k0 + tx] = __float2bfloat16(v - __bfloat162float(h));
    }
}

// ---------------------------------------------------------------------------
// proj_mma: 128x128 output tile per CTA via mma.sync bf16 3-pass hi/lo split.
//   D = Ah@Bh^T + Ah@Bl^T + Al@Bh^T   (fp32 accumulators)
// 8 warps = 2(m) x 4(n); each warp 64x32 (4 m-frags x 4 n-frags).
// KC=32 chunks, register-prefetch double buffering.
// ---------------------------------------------------------------------------
#define KC 32
#define NCHUNK (DM / KC)   // 32
#define SPAD 40            // smem row stride in bf16 (conflict-free for frag loads)

__global__ __launch_bounds__(256) void proj_mma(const float* __restrict__ bq,
                                                const float* __restrict__ bk,
                                                const float* __restrict__ bv)
{
    __shared__ __nv_bfloat16 sAh[128][SPAD];
    __shared__ __nv_bfloat16 sAl[128][SPAD];
    __shared__ __nv_bfloat16 sBh[128][SPAD];
    __shared__ __nv_bfloat16 sBl[128][SPAD];

    int tid = threadIdx.x;
    int wid = tid >> 5, lane = tid & 31;
    int g = lane >> 2, tig = lane & 3;
    int wm = wid >> 2, wn = wid & 3;             // 2 x 4 warp grid
    int n0 = blockIdx.x * 128;
    int m0 = blockIdx.y * 128;
    int mat = blockIdx.z;

    const float* bias = (mat == 0) ? bq : (mat == 1) ? bk : bv;
    float* outp = (mat == 0) ? g_q : (mat == 1) ? g_k : g_v;
    const __nv_bfloat16* ah = g_xh + (size_t)m0 * DM;
    const __nv_bfloat16* al = g_xl + (size_t)m0 * DM;
    const __nv_bfloat16* bh = g_wth + (size_t)mat * DM * DM + (size_t)n0 * DM;
    const __nv_bfloat16* bl = g_wtl + (size_t)mat * DM * DM + (size_t)n0 * DM;

    float acc[4][4][4];
    #pragma unroll
    for (int i = 0; i < 4; i++)
        #pragma unroll
        for (int j = 0; j < 4; j++)
            #pragma unroll
            for (int r = 0; r < 4; r++) acc[i][j][r] = 0.f;

    // prefetch registers: 4 tiles x 2 segments (each uint4 = 8 bf16)
    uint4 pf[4][2];
    // thread -> (row, seg): i = tid + j*256; r = i>>2; seg = i&3 (seg of 8 bf16)
    int r0 = tid >> 2, sg0 = (tid & 3) * 8;
    int r1 = (tid + 256) >> 2, sg1 = ((tid + 256) & 3) * 8;

    const __nv_bfloat16* srcs[4] = {ah, al, bh, bl};

    // load chunk 0
    #pragma unroll
    for (int a = 0; a < 4; a++) {
        pf[a][0] = *(const uint4*)(srcs[a] + (size_t)r0 * DM + sg0);
        pf[a][1] = *(const uint4*)(srcs[a] + (size_t)r1 * DM + sg1);
    }
    {
        *(uint4*)&sAh[r0][sg0] = pf[0][0]; *(uint4*)&sAh[r1][sg1] = pf[0][1];
        *(uint4*)&sAl[r0][sg0] = pf[1][0]; *(uint4*)&sAl[r1][sg1] = pf[1][1];
        *(uint4*)&sBh[r0][sg0] = pf[2][0]; *(uint4*)&sBh[r1][sg1] = pf[2][1];
        *(uint4*)&sBl[r0][sg0] = pf[3][0]; *(uint4*)&sBl[r1][sg1] = pf[3][1];
    }
    __syncthreads();

    #pragma unroll 1
    for (int c = 0; c < NCHUNK; c++) {
        // issue global loads for next chunk (overlap with compute)
        if (c + 1 < NCHUNK) {
            int k0 = (c + 1) * KC;
            #pragma unroll
            for (int a = 0; a < 4; a++) {
                pf[a][0] = *(const uint4*)(srcs[a] + (size_t)r0 * DM + k0 + sg0);
                pf[a][1] = *(const uint4*)(srcs[a] + (size_t)r1 * DM + k0 + sg1);
            }
        }

        // compute 2 k16 steps from smem
        #pragma unroll
        for (int kk = 0; kk < 2; kk++) {
            int kof = kk * 16 + tig * 2;
            // B fragments (4 n-frags, hi & lo)
            uint32_t vbh[4][2], vbl[4][2];
            #pragma unroll
            for (int nf = 0; nf < 4; nf++) {
                int brow = wn * 32 + nf * 8 + g;
                vbh[nf][0] = *(const uint32_t*)&sBh[brow][kof];
                vbh[nf][1] = *(const uint32_t*)&sBh[brow][kof + 8];
                vbl[nf][0] = *(const uint32_t*)&sBl[brow][kof];
                vbl[nf][1] = *(const uint32_t*)&sBl[brow][kof + 8];
            }
            #pragma unroll
            for (int mf = 0; mf < 4; mf++) {
                int ar = wm * 64 + mf * 16 + g;
                uint32_t ah0 = *(const uint32_t*)&sAh[ar][kof];
                uint32_t ah1 = *(const uint32_t*)&sAh[ar + 8][kof];
                uint32_t ah2 = *(const uint32_t*)&sAh[ar][kof + 8];
                uint32_t ah3 = *(const uint32_t*)&sAh[ar + 8][kof + 8];
                uint32_t al0 = *(const uint32_t*)&sAl[ar][kof];
                uint32_t al1 = *(const uint32_t*)&sAl[ar + 8][kof];
                uint32_t al2 = *(const uint32_t*)&sAl[ar][kof + 8];
                uint32_t al3 = *(const uint32_t*)&sAl[ar + 8][kof + 8];
                #pragma unroll
                for (int nf = 0; nf < 4; nf++) {
                    MMA16816(acc[mf][nf], ah0, ah1, ah2, ah3, vbh[nf][0], vbh[nf][1]);
                    MMA16816(acc[mf][nf], ah0, ah1, ah2, ah3, vbl[nf][0], vbl[nf][1]);
                    MMA16816(acc[mf][nf], al0, al1, al2, al3, vbh[nf][0], vbh[nf][1]);
                }
            }
        }
        __syncthreads();
        if (c + 1 < NCHUNK) {
            *(uint4*)&sAh[r0][sg0] = pf[0][0]; *(uint4*)&sAh[r1][sg1] = pf[0][1];
            *(uint4*)&sAl[r0][sg0] = pf[1][0]; *(uint4*)&sAl[r1][sg1] = pf[1][1];
            *(uint4*)&sBh[r0][sg0] = pf[2][0]; *(uint4*)&sBh[r1][sg1] = pf[2][1];
            *(uint4*)&sBl[r0][sg0] = pf[3][0]; *(uint4*)&sBl[r1][sg1] = pf[3][1];
            __syncthreads();
        }
    }

    // Epilogue: bias + scatter to [b,h,t,d]
    #pragma unroll
    for (int mf = 0; mf < 4; mf++) {
        #pragma unroll
        for (int nf = 0; nf < 4; nf++) {
            int n = n0 + wn * 32 + nf * 8 + tig * 2;
            int h = n >> 6, d = n & 63;
            float b0 = bias[n], b1 = bias[n + 1];
            #pragma unroll
            for (int half = 0; half < 2; half++) {
                int m = m0 + wm * 64 + mf * 16 + g + half * 8;
                int b = m >> 10, t = m & 1023;
                float* op = &outp[(((size_t)b * HEADS + h) * T_LEN + t) * DH + d];
                float2 v = make_float2(acc[mf][nf][half * 2] + b0,
                                       acc[mf][nf][half * 2 + 1] + b1);
                *(float2*)op = v;
            }
        }
    }
}

// ---------------------------------------------------------------------------
// Relative scores: R[bh][t][c] = q[bh][t] . Er[c]  (banded; fp32 SIMT)
// ---------------------------------------------------------------------------
__global__ __launch_bounds__(256) void rel_kernel(const float* __restrict__ Er)
{
    int sb = blockIdx.x, tb = blockIdx.y, bh = blockIdx.z;
    if (tb + sb < 15) return;   // tile never read under causal mask

    __shared__ float qs[64][68];
    __shared__ float es[64][68];

    int t0 = tb * 64, s0 = sb * 64;
    const float* qg = g_q + (size_t)bh * T_LEN * DH;

    int tid = threadIdx.x;
    int tx = tid & 15, ty = tid >> 4;
    int r4 = ty * 4, c4 = tx * 4;

    for (int idx = tid; idx < 4096; idx += 256) {
        int r = idx >> 6, c = idx & 63;
        qs[r][c] = qg[(t0 + r) * DH + c];
        es[c][r] = Er[(s0 + r) * DH + c];
    }
    __syncthreads();

    float acc[4][4];
    #pragma unroll
    for (int i = 0; i < 4; i++)
        #pragma unroll
        for (int j = 0; j < 4; j++) acc[i][j] = 0.f;

    #pragma unroll 16
    for (int d = 0; d < 64; d++) {
        float4 b4 = *(const float4*)&es[d][c4];
        #pragma unroll
        for (int i = 0; i < 4; i++) {
            float a = qs[r4 + i][d];
            acc[i][0] += a * b4.x; acc[i][1] += a * b4.y;
            acc[i][2] += a * b4.z; acc[i][3] += a * b4.w;
        }
    }

    float* Rg = g_R + (size_t)bh * T_LEN * T_LEN;
    #pragma unroll
    for (int i = 0; i < 4; i++)
        *(float4*)&Rg[(size_t)(t0 + r4 + i) * T_LEN + s0 + c4] =
            make_float4(acc[i][0], acc[i][1], acc[i][2], acc[i][3]);
}

// ---------------------------------------------------------------------------
// Flash attention with relative-position gather (fp32 SIMT).
// ---------------------------------------------------------------------------
#define AT_SMEM_BYTES (3 * 64 * 68 * 4)

__global__ __launch_bounds__(256) void attn_kernel(float* __restrict__ out)
{
    extern __shared__ float smf[];
    float (*q_s)[68]  = (float(*)[68])(smf);
    float (*kv_s)[68] = (float(*)[68])(smf + 64 * 68);
    float (*p_s)[68]  = (float(*)[68])(smf + 2 * 64 * 68);

    int tb = blockIdx.x;
    int bh = blockIdx.y;
    int t0 = tb * 64;

    const float* qg = g_q + (size_t)bh * T_LEN * DH;
    const float* kg = g_k + (size_t)bh * T_LEN * DH;
    const float* vg = g_v + (size_t)bh * T_LEN * DH;
    const float* Rg = g_R + (size_t)bh * T_LEN * T_LEN;

    int tid = threadIdx.x;
    int tx = tid & 15, ty = tid >> 4;
    int r4 = ty * 4, c4 = tx * 4;

    for (int idx = tid; idx < 4096; idx += 256) {
        int r = idx >> 6, c = idx & 63;
        q_s[r][c] = qg[(t0 + r) * DH + c];
    }

    float m_i[4], l_i[4], o_acc[4][4];
    #pragma unroll
    for (int i = 0; i < 4; i++) {
        m_i[i] = -1e30f; l_i[i] = 0.f;
        #pragma unroll
        for (int j = 0; j < 4; j++) o_acc[i][j] = 0.f;
    }

    for (int sb = 0; sb <= tb; sb++) {
        int s0 = sb * 64;
        __syncthreads();
        for (int idx = tid; idx < 4096; idx += 256) {
            int j = idx >> 6, d = idx & 63;
            kv_s[d][j] = kg[(s0 + j) * DH + d];
        }
        __syncthreads();

        float s_t[4][4];
        #pragma unroll
        for (int i = 0; i < 4; i++)
            #pragma unroll
            for (int j = 0; j < 4; j++) s_t[i][j] = 0.f;

        #pragma unroll 16
        for (int d = 0; d < 64; d++) {
            float4 b4 = *(const float4*)&kv_s[d][c4];
            #pragma unroll
            for (int i = 0; i < 4; i++) {
                float a = q_s[r4 + i][d];
                s_t[i][0] += a * b4.x; s_t[i][1] += a * b4.y;
                s_t[i][2] += a * b4.z; s_t[i][3] += a * b4.w;
            }
        }

        #pragma unroll
        for (int i = 0; i < 4; i++) {
            int t = t0 + r4 + i;
            const float* Rrow = Rg + (size_t)t * T_LEN + (T_LEN - 1 - t);
            #pragma unroll
            for (int j = 0; j < 4; j++) {
                int s = s0 + c4 + j;
                if (s <= t)
                    s_t[i][j] = (s_t[i][j] + Rrow[s]) * 0.125f;
                else
                    s_t[i][j] = -1e30f;
            }
        }

        #pragma unroll
        for (int i = 0; i < 4; i++) {
            float mx = fmaxf(fmaxf(s_t[i][0], s_t[i][1]), fmaxf(s_t[i][2], s_t[i][3]));
            #pragma unroll
            for (int off = 8; off >= 1; off >>= 1)
                mx = fmaxf(mx, __shfl_xor_sync(0xffffffffu, mx, off));
            float mn = fmaxf(m_i[i], mx);
            float alpha = __expf(m_i[i] - mn);
            m_i[i] = mn;
            float rs = 0.f;
            #pragma unroll
            for (int j = 0; j < 4; j++) {
                float p = __expf(s_t[i][j] - mn);
                s_t[i][j] = p; rs += p;
            }
            #pragma unroll
            for (int off = 8; off >= 1; off >>= 1)
                rs += __shfl_xor_sync(0xffffffffu, rs, off);
            l_i[i] = l_i[i] * alpha + rs;
            #pragma unroll
            for (int j = 0; j < 4; j++) o_acc[i][j] *= alpha;
        }

        #pragma unroll
        for (int i = 0; i < 4; i++)
            *(float4*)&p_s[r4 + i][c4] =
                make_float4(s_t[i][0], s_t[i][1], s_t[i][2], s_t[i][3]);
        __syncthreads();

        for (int idx = tid; idx < 4096; idx += 256) {
            int j = idx >> 6, d = idx & 63;
            kv_s[j][d] = vg[(s0 + j) * DH + d];
        }
        __syncthreads();

        #pragma unroll 16
        for (int j = 0; j < 64; j++) {
            float4 v4 = *(const float4*)&kv_s[j][c4];
            #pragma unroll
            for (int i = 0; i < 4; i++) {
                float p = p_s[r4 + i][j];
                o_acc[i][0] += p * v4.x; o_acc[i][1] += p * v4.y;
                o_acc[i][2] += p * v4.z; o_acc[i][3] += p * v4.w;
            }
        }
    }

    int b = bh >> 4, h = bh & 15;
    #pragma unroll
    for (int i = 0; i < 4; i++) {
        int t = t0 + r4 + i;
        float inv = 1.f / l_i[i];
        float* op = out + ((size_t)b * T_LEN + t) * (HEADS * DH) + h * DH + c4;
        *(float4*)op = make_float4(o_acc[i][0] * inv, o_acc[i][1] * inv,
                                   o_acc[i][2] * inv, o_acc[i][3] * inv);
    }
}

// ---------------------------------------------------------------------------
extern "C" void kernel_launch(void* const* d_in, const int* in_sizes, int n_in,
                              void* d_out, int out_size)
{
    const float* x  = (const float*)d_in[0];
    const float* Wq = (const float*)d_in[1];
    const float* bq = (const float*)d_in[2];
    const float* Wk = (const float*)d_in[3];
    const float* bk = (const float*)d_in[4];
    const float* Wv = (const float*)d_in[5];
    const float* bv = (const float*)d_in[6];
    const float* Er = (const float*)d_in[7];
    float* out = (float*)d_out;

    int NB = in_sizes[0] / (T_LEN * DM);
    if (NB > NB_MAX) NB = NB_MAX;

    cudaFuncSetAttribute(attn_kernel, cudaFuncAttributeMaxDynamicSharedMemorySize,
                         AT_SMEM_BYTES);

    // 0) split x / transpose+split W to bf16 hi/lo
    int n4 = NB * T_LEN * DM / 4;
    prep_x<<<(n4 + 255) / 256, 256>>>(x, n4);
    prep_w<<<dim3(32, 32, 3), dim3(32, 8)>>>(Wq, Wk, Wv);

    // 1) q,k,v projections on HMMA (3-pass bf16 split)
    dim3 pgrid(8, NB * 8, 3);
    proj_mma<<<pgrid, 256>>>(bq, bk, bv);

    // 2) relative scores R = q @ Er^T (banded)
    dim3 rgrid(16, 16, NB * HEADS);
    rel_kernel<<<rgrid, 256>>>(Er);

    // 3) flash attention + rel gather + output merge
    dim3 agrid(16, NB * HEADS);
    attn_kernel<<<agrid, 256, AT_SMEM_BYTES>>>(out);
}

// round 6
// speedup vs baseline: 1.5285x; 1.1764x over previous
#include <cuda_runtime.h>
#include <cuda_bf16.h>
#include <cstdint>

// Problem constants (fixed by the reference: N=4, T=1024, H=16, D_HEAD=64)
#define T_LEN 1024
#define HEADS 16
#define DH 64
#define NB_MAX 4
#define DM 1024

// ---------------------------------------------------------------------------
// Scratch (device globals — no allocation allowed in kernel_launch)
// ---------------------------------------------------------------------------
__device__ __align__(16) float g_R[(size_t)NB_MAX * HEADS * T_LEN * T_LEN]; // [bh][t][c], c=s-t+1023
// bf16 hi/lo split operands
__device__ __align__(16) __nv_bfloat16 g_xh[NB_MAX * T_LEN * DM];
__device__ __align__(16) __nv_bfloat16 g_xl[NB_MAX * T_LEN * DM];
__device__ __align__(16) __nv_bfloat16 g_wth[3 * DM * DM];  // W^T [mat][n][k]
__device__ __align__(16) __nv_bfloat16 g_wtl[3 * DM * DM];
__device__ __align__(16) __nv_bfloat16 g_qh[NB_MAX * HEADS * T_LEN * DH];
__device__ __align__(16) __nv_bfloat16 g_ql[NB_MAX * HEADS * T_LEN * DH];
__device__ __align__(16) __nv_bfloat16 g_kh[NB_MAX * HEADS * T_LEN * DH];
__device__ __align__(16) __nv_bfloat16 g_kl[NB_MAX * HEADS * T_LEN * DH];
__device__ __align__(16) __nv_bfloat16 g_vh[NB_MAX * HEADS * T_LEN * DH];
__device__ __align__(16) __nv_bfloat16 g_vl[NB_MAX * HEADS * T_LEN * DH];
__device__ __align__(16) __nv_bfloat16 g_erh[T_LEN * DH];
__device__ __align__(16) __nv_bfloat16 g_erl[T_LEN * DH];

// mma.sync m16n8k16 row.col f32.bf16.bf16.f32 (base PTX — works on sm_100)
#define MMA16816(d, a0, a1, a2, a3, b0, b1)                                   \
    asm volatile(                                                             \
        "mma.sync.aligned.m16n8k16.row.col.f32.bf16.bf16.f32 "                \
        "{%0,%1,%2,%3}, {%4,%5,%6,%7}, {%8,%9}, {%0,%1,%2,%3};"               \
        : "+f"((d)[0]), "+f"((d)[1]), "+f"((d)[2]), "+f"((d)[3])              \
        : "r"(a0), "r"(a1), "r"(a2), "r"(a3), "r"(b0), "r"(b1))

__device__ __forceinline__ uint32_t pack_bf16(__nv_bfloat16 a, __nv_bfloat16 b) {
    __nv_bfloat162 t = __halves2bfloat162(a, b);
    return *(uint32_t*)&t;
}
__device__ __forceinline__ uint32_t pack_f2bf(float a, float b) {
    __nv_bfloat162 t = __floats2bfloat162_rn(a, b);
    return *(uint32_t*)&t;
}

// ---------------------------------------------------------------------------
// prep_x: fp32 x -> bf16 hi/lo (same [m][k] layout)
// ---------------------------------------------------------------------------
__global__ __launch_bounds__(256) void prep_x(const float* __restrict__ x, int n4)
{
    int i = blockIdx.x * 256 + threadIdx.x;
    if (i >= n4) return;
    float4 v = ((const float4*)x)[i];
    __nv_bfloat16 h[4], l[4];
    float f[4] = {v.x, v.y, v.z, v.w};
    #pragma unroll
    for (int j = 0; j < 4; j++) {
        h[j] = __float2bfloat16(f[j]);
        l[j] = __float2bfloat16(f[j] - __bfloat162float(h[j]));
    }
    __nv_bfloat162* oh = (__nv_bfloat162*)g_xh;
    __nv_bfloat162* ol = (__nv_bfloat162*)g_xl;
    oh[2 * i]     = __halves2bfloat162(h[0], h[1]);
    oh[2 * i + 1] = __halves2bfloat162(h[2], h[3]);
    ol[2 * i]     = __halves2bfloat162(l[0], l[1]);
    ol[2 * i + 1] = __halves2bfloat162(l[2], l[3]);
}

// prep_er: fp32 Er -> bf16 hi/lo
__global__ __launch_bounds__(256) void prep_er(const float* __restrict__ er)
{
    int i = blockIdx.x * 256 + threadIdx.x;     // over float4, 16384 total
    if (i >= T_LEN * DH / 4) return;
    float4 v = ((const float4*)er)[i];
    float f[4] = {v.x, v.y, v.z, v.w};
    __nv_bfloat16 h[4], l[4];
    #pragma unroll
    for (int j = 0; j < 4; j++) {
        h[j] = __float2bfloat16(f[j]);
        l[j] = __float2bfloat16(f[j] - __bfloat162float(h[j]));
    }
    __nv_bfloat162* oh = (__nv_bfloat162*)g_erh;
    __nv_bfloat162* ol = (__nv_bfloat162*)g_erl;
    oh[2 * i]     = __halves2bfloat162(h[0], h[1]);
    oh[2 * i + 1] = __halves2bfloat162(h[2], h[3]);
    ol[2 * i]     = __halves2bfloat162(l[0], l[1]);
    ol[2 * i + 1] = __halves2bfloat162(l[2], l[3]);
}

// ---------------------------------------------------------------------------
// prep_w: transpose W [k][n] -> W^T [n][k], split to bf16 hi/lo
// ---------------------------------------------------------------------------
__global__ __launch_bounds__(256) void prep_w(const float* __restrict__ Wq,
                                              const float* __restrict__ Wk,
                                              const float* __restrict__ Wv)
{
    const float* W = (blockIdx.z == 0) ? Wq : (blockIdx.z == 1) ? Wk : Wv;
    __shared__ float t[32][33];
    int tx = threadIdx.x, ty = threadIdx.y;        // 32 x 8
    int n0 = blockIdx.x * 32, k0 = blockIdx.y * 32;
    #pragma unroll
    for (int i = 0; i < 4; i++)
        t[ty + 8 * i][tx] = W[(size_t)(k0 + ty + 8 * i) * DM + n0 + tx];
    __syncthreads();
    __nv_bfloat16* oh = g_wth + (size_t)blockIdx.z * DM * DM;
    __nv_bfloat16* ol = g_wtl + (size_t)blockIdx.z * DM * DM;
    #pragma unroll
    for (int i = 0; i < 4; i++) {
        int n = n0 + ty + 8 * i;
        float v = t[tx][ty + 8 * i];
        __nv_bfloat16 h = __float2bfloat16(v);
        oh[(size_t)n * DM + k0 + tx] = h;
        ol[(size_t)n * DM + k0 + tx] = __float2bfloat16(v - __bfloat162float(h));
    }
}

// ---------------------------------------------------------------------------
// proj_mma: 128x128 output tile per CTA via mma.sync bf16 3-pass hi/lo split.
// Epilogue writes q/k/v as bf16 hi/lo pairs (operands for rel/attn HMMA).
// ---------------------------------------------------------------------------
#define KC 32
#define NCHUNK (DM / KC)   // 32
#define SPAD 40            // smem row stride in bf16 (conflict-free for frag loads)

__global__ __launch_bounds__(256) void proj_mma(const float* __restrict__ bq,
                                                const float* __restrict__ bk,
                                                const float* __restrict__ bv)
{
    __shared__ __nv_bfloat16 sAh[128][SPAD];
    __shared__ __nv_bfloat16 sAl[128][SPAD];
    __shared__ __nv_bfloat16 sBh[128][SPAD];
    __shared__ __nv_bfloat16 sBl[128][SPAD];

    int tid = threadIdx.x;
    int wid = tid >> 5, lane = tid & 31;
    int g = lane >> 2, tig = lane & 3;
    int wm = wid >> 2, wn = wid & 3;             // 2 x 4 warp grid
    int n0 = blockIdx.x * 128;
    int m0 = blockIdx.y * 128;
    int mat = blockIdx.z;

    const float* bias = (mat == 0) ? bq : (mat == 1) ? bk : bv;
    __nv_bfloat16* outh = (mat == 0) ? g_qh : (mat == 1) ? g_kh : g_vh;
    __nv_bfloat16* outl = (mat == 0) ? g_ql : (mat == 1) ? g_kl : g_vl;
    const __nv_bfloat16* ah = g_xh + (size_t)m0 * DM;
    const __nv_bfloat16* al = g_xl + (size_t)m0 * DM;
    const __nv_bfloat16* bh = g_wth + (size_t)mat * DM * DM + (size_t)n0 * DM;
    const __nv_bfloat16* bl = g_wtl + (size_t)mat * DM * DM + (size_t)n0 * DM;

    float acc[4][4][4];
    #pragma unroll
    for (int i = 0; i < 4; i++)
        #pragma unroll
        for (int j = 0; j < 4; j++)
            #pragma unroll
            for (int r = 0; r < 4; r++) acc[i][j][r] = 0.f;

    uint4 pf[4][2];
    int r0 = tid >> 2, sg0 = (tid & 3) * 8;
    int r1 = (tid + 256) >> 2, sg1 = ((tid + 256) & 3) * 8;

    const __nv_bfloat16* srcs[4] = {ah, al, bh, bl};

    #pragma unroll
    for (int a = 0; a < 4; a++) {
        pf[a][0] = *(const uint4*)(srcs[a] + (size_t)r0 * DM + sg0);
        pf[a][1] = *(const uint4*)(srcs[a] + (size_t)r1 * DM + sg1);
    }
    {
        *(uint4*)&sAh[r0][sg0] = pf[0][0]; *(uint4*)&sAh[r1][sg1] = pf[0][1];
        *(uint4*)&sAl[r0][sg0] = pf[1][0]; *(uint4*)&sAl[r1][sg1] = pf[1][1];
        *(uint4*)&sBh[r0][sg0] = pf[2][0]; *(uint4*)&sBh[r1][sg1] = pf[2][1];
        *(uint4*)&sBl[r0][sg0] = pf[3][0]; *(uint4*)&sBl[r1][sg1] = pf[3][1];
    }
    __syncthreads();

    #pragma unroll 1
    for (int c = 0; c < NCHUNK; c++) {
        if (c + 1 < NCHUNK) {
            int k0 = (c + 1) * KC;
            #pragma unroll
            for (int a = 0; a < 4; a++) {
                pf[a][0] = *(const uint4*)(srcs[a] + (size_t)r0 * DM + k0 + sg0);
                pf[a][1] = *(const uint4*)(srcs[a] + (size_t)r1 * DM + k0 + sg1);
            }
        }
        #pragma unroll
        for (int kk = 0; kk < 2; kk++) {
            int kof = kk * 16 + tig * 2;
            uint32_t vbh[4][2], vbl[4][2];
            #pragma unroll
            for (int nf = 0; nf < 4; nf++) {
                int brow = wn * 32 + nf * 8 + g;
                vbh[nf][0] = *(const uint32_t*)&sBh[brow][kof];
                vbh[nf][1] = *(const uint32_t*)&sBh[brow][kof + 8];
                vbl[nf][0] = *(const uint32_t*)&sBl[brow][kof];
                vbl[nf][1] = *(const uint32_t*)&sBl[brow][kof + 8];
            }
            #pragma unroll
            for (int mf = 0; mf < 4; mf++) {
                int ar = wm * 64 + mf * 16 + g;
                uint32_t ah0 = *(const uint32_t*)&sAh[ar][kof];
                uint32_t ah1 = *(const uint32_t*)&sAh[ar + 8][kof];
                uint32_t ah2 = *(const uint32_t*)&sAh[ar][kof + 8];
                uint32_t ah3 = *(const uint32_t*)&sAh[ar + 8][kof + 8];
                uint32_t al0 = *(const uint32_t*)&sAl[ar][kof];
                uint32_t al1 = *(const uint32_t*)&sAl[ar + 8][kof];
                uint32_t al2 = *(const uint32_t*)&sAl[ar][kof + 8];
                uint32_t al3 = *(const uint32_t*)&sAl[ar + 8][kof + 8];
                #pragma unroll
                for (int nf = 0; nf < 4; nf++) {
                    MMA16816(acc[mf][nf], ah0, ah1, ah2, ah3, vbh[nf][0], vbh[nf][1]);
                    MMA16816(acc[mf][nf], ah0, ah1, ah2, ah3, vbl[nf][0], vbl[nf][1]);
                    MMA16816(acc[mf][nf], al0, al1, al2, al3, vbh[nf][0], vbh[nf][1]);
                }
            }
        }
        __syncthreads();
        if (c + 1 < NCHUNK) {
            *(uint4*)&sAh[r0][sg0] = pf[0][0]; *(uint4*)&sAh[r1][sg1] = pf[0][1];
            *(uint4*)&sAl[r0][sg0] = pf[1][0]; *(uint4*)&sAl[r1][sg1] = pf[1][1];
            *(uint4*)&sBh[r0][sg0] = pf[2][0]; *(uint4*)&sBh[r1][sg1] = pf[2][1];
            *(uint4*)&sBl[r0][sg0] = pf[3][0]; *(uint4*)&sBl[r1][sg1] = pf[3][1];
            __syncthreads();
        }
    }

    // Epilogue: bias + split to bf16 hi/lo + scatter to [b,h,t,d]
    #pragma unroll
    for (int mf = 0; mf < 4; mf++) {
        #pragma unroll
        for (int nf = 0; nf < 4; nf++) {
            int n = n0 + wn * 32 + nf * 8 + tig * 2;
            int h = n >> 6, d = n & 63;
            float b0 = bias[n], b1 = bias[n + 1];
            #pragma unroll
            for (int half = 0; half < 2; half++) {
                int m = m0 + wm * 64 + mf * 16 + g + half * 8;
                int b = m >> 10, t = m & 1023;
                size_t idx = (((size_t)b * HEADS + h) * T_LEN + t) * DH + d;
                float v0 = acc[mf][nf][half * 2] + b0;
                float v1 = acc[mf][nf][half * 2 + 1] + b1;
                __nv_bfloat16 h0 = __float2bfloat16(v0);
                __nv_bfloat16 h1 = __float2bfloat16(v1);
                *(uint32_t*)&outh[idx] = pack_bf16(h0, h1);
                *(uint32_t*)&outl[idx] = pack_f2bf(v0 - __bfloat162float(h0),
                                                   v1 - __bfloat162float(h1));
            }
        }
    }
}

// ---------------------------------------------------------------------------
// rel_mma: banded R[bh][t][c] = q[bh][t].Er[c] on HMMA (3-pass hi/lo).
// Block 128 thr (4 warps x 16 rows). 64x64 tile.
// ---------------------------------------------------------------------------
#define EPAD 72

__global__ __launch_bounds__(128) void rel_mma()
{
    __shared__ __nv_bfloat16 sEh[64][EPAD];
    __shared__ __nv_bfloat16 sEl[64][EPAD];

    int sb = blockIdx.x, tb = blockIdx.y, bh = blockIdx.z;
    if (tb + sb < 15) return;   // tile never read under causal mask

    int tid = threadIdx.x, w = tid >> 5, lane = tid & 31;
    int g = lane >> 2, tig = lane & 3;
    int t0 = tb * 64, s0 = sb * 64;

    const __nv_bfloat16* qh = g_qh + (size_t)bh * T_LEN * DH;
    const __nv_bfloat16* ql = g_ql + (size_t)bh * T_LEN * DH;

    // load Er tile to smem
    for (int i = tid; i < 512; i += 128) {
        int r = i >> 3, c = (i & 7) * 8;
        *(uint4*)&sEh[r][c] = *(const uint4*)&g_erh[(s0 + r) * DH + c];
        *(uint4*)&sEl[r][c] = *(const uint4*)&g_erl[(s0 + r) * DH + c];
    }

    // load Q fragments (rows t0+16w+g, +8)
    int rowA = t0 + w * 16 + g;
    uint32_t qfh[4][4], qfl[4][4];
    #pragma unroll
    for (int ks = 0; ks < 4; ks++) {
        int d0 = ks * 16 + tig * 2;
        qfh[ks][0] = *(const uint32_t*)&qh[(size_t)rowA * DH + d0];
        qfh[ks][1] = *(const uint32_t*)&qh[(size_t)(rowA + 8) * DH + d0];
        qfh[ks][2] = *(const uint32_t*)&qh[(size_t)rowA * DH + d0 + 8];
        qfh[ks][3] = *(const uint32_t*)&qh[(size_t)(rowA + 8) * DH + d0 + 8];
        qfl[ks][0] = *(const uint32_t*)&ql[(size_t)rowA * DH + d0];
        qfl[ks][1] = *(const uint32_t*)&ql[(size_t)(rowA + 8) * DH + d0];
        qfl[ks][2] = *(const uint32_t*)&ql[(size_t)rowA * DH + d0 + 8];
        qfl[ks][3] = *(const uint32_t*)&ql[(size_t)(rowA + 8) * DH + d0 + 8];
    }
    __syncthreads();

    float acc[8][4];
    #pragma unroll
    for (int f = 0; f < 8; f++)
        #pragma unroll
        for (int r = 0; r < 4; r++) acc[f][r] = 0.f;

    #pragma unroll
    for (int ks = 0; ks < 4; ks++) {
        int kb = ks * 16 + tig * 2;
        #pragma unroll
        for (int nf = 0; nf < 8; nf++) {
            int br = nf * 8 + g;
            uint32_t bh0 = *(const uint32_t*)&sEh[br][kb];
            uint32_t bh1 = *(const uint32_t*)&sEh[br][kb + 8];
            uint32_t bl0 = *(const uint32_t*)&sEl[br][kb];
            uint32_t bl1 = *(const uint32_t*)&sEl[br][kb + 8];
            MMA16816(acc[nf], qfh[ks][0], qfh[ks][1], qfh[ks][2], qfh[ks][3], bh0, bh1);
            MMA16816(acc[nf], qfh[ks][0], qfh[ks][1], qfh[ks][2], qfh[ks][3], bl0, bl1);
            MMA16816(acc[nf], qfl[ks][0], qfl[ks][1], qfl[ks][2], qfl[ks][3], bh0, bh1);
        }
    }

    float* Rg = g_R + (size_t)bh * T_LEN * T_LEN;
    #pragma unroll
    for (int nf = 0; nf < 8; nf++) {
        int c = s0 + nf * 8 + tig * 2;
        *(float2*)&Rg[(size_t)rowA * T_LEN + c] = make_float2(acc[nf][0], acc[nf][1]);
        *(float2*)&Rg[(size_t)(rowA + 8) * T_LEN + c] = make_float2(acc[nf][2], acc[nf][3]);
    }
}

// ---------------------------------------------------------------------------
// attn_mma: FA2-style flash attention on HMMA (3-pass hi/lo for QK and PV).
// Block 128 thr (4 warps x 16 t-rows = 64-row t-tile). K natural, V transposed.
// ---------------------------------------------------------------------------
__global__ __launch_bounds__(128) void attn_mma(float* __restrict__ out)
{
    __shared__ __nv_bfloat16 sKh[64][EPAD];
    __shared__ __nv_bfloat16 sKl[64][EPAD];
    __shared__ __nv_bfloat16 sVh[64][EPAD];   // transposed [d][s]
    __shared__ __nv_bfloat16 sVl[64][EPAD];

    int tid = threadIdx.x, w = tid >> 5, lane = tid & 31;
    int g = lane >> 2, tig = lane & 3;
    int tb = blockIdx.x, bh = blockIdx.y;
    int t0 = tb * 64;

    const __nv_bfloat16* qh = g_qh + (size_t)bh * T_LEN * DH;
    const __nv_bfloat16* ql = g_ql + (size_t)bh * T_LEN * DH;
    const __nv_bfloat16* kh = g_kh + (size_t)bh * T_LEN * DH;
    const __nv_bfloat16* kl = g_kl + (size_t)bh * T_LEN * DH;
    const __nv_bfloat16* vh = g_vh + (size_t)bh * T_LEN * DH;
    const __nv_bfloat16* vl = g_vl + (size_t)bh * T_LEN * DH;
    const float* Rg = g_R + (size_t)bh * T_LEN * T_LEN;

    int rowA = t0 + w * 16 + g;          // this thread's row pair: rowA, rowA+8
    int row1 = rowA + 8;

    // Q fragments (held for the whole kernel)
    uint32_t qfh[4][4], qfl[4][4];
    #pragma unroll
    for (int ks = 0; ks < 4; ks++) {
        int d0 = ks * 16 + tig * 2;
        qfh[ks][0] = *(const uint32_t*)&qh[(size_t)rowA * DH + d0];
        qfh[ks][1] = *(const uint32_t*)&qh[(size_t)row1 * DH + d0];
        qfh[ks][2] = *(const uint32_t*)&qh[(size_t)rowA * DH + d0 + 8];
        qfh[ks][3] = *(const uint32_t*)&qh[(size_t)row1 * DH + d0 + 8];
        qfl[ks][0] = *(const uint32_t*)&ql[(size_t)rowA * DH + d0];
        qfl[ks][1] = *(const uint32_t*)&ql[(size_t)row1 * DH + d0];
        qfl[ks][2] = *(const uint32_t*)&ql[(size_t)rowA * DH + d0 + 8];
        qfl[ks][3] = *(const uint32_t*)&ql[(size_t)row1 * DH + d0 + 8];
    }

    float m0 = -1e30f, m1 = -1e30f, l0 = 0.f, l1 = 0.f;
    float o[8][4];
    #pragma unroll
    for (int f = 0; f < 8; f++)
        #pragma unroll
        for (int r = 0; r < 4; r++) o[f][r] = 0.f;

    const float* R0 = Rg + (size_t)rowA * T_LEN + (T_LEN - 1 - rowA);
    const float* R1 = Rg + (size_t)row1 * T_LEN + (T_LEN - 1 - row1);

    #pragma unroll 1
    for (int sb = 0; sb <= tb; sb++) {
        int s0 = sb * 64;
        __syncthreads();      // prior iteration done with smem
        // K tile (natural [s][d])
        for (int i = tid; i < 512; i += 128) {
            int r = i >> 3, c = (i & 7) * 8;
            *(uint4*)&sKh[r][c] = *(const uint4*)&kh[(size_t)(s0 + r) * DH + c];
            *(uint4*)&sKl[r][c] = *(const uint4*)&kl[(size_t)(s0 + r) * DH + c];
        }
        // V tile transposed ([d][s])
        for (int i = tid; i < 2048; i += 128) {
            int j = i >> 5, d2 = (i & 31) * 2;
            __nv_bfloat162 a = *(const __nv_bfloat162*)&vh[(size_t)(s0 + j) * DH + d2];
            sVh[d2][j] = a.x; sVh[d2 + 1][j] = a.y;
            __nv_bfloat162 b2 = *(const __nv_bfloat162*)&vl[(size_t)(s0 + j) * DH + d2];
            sVl[d2][j] = b2.x; sVl[d2 + 1][j] = b2.y;
        }
        __syncthreads();

        // S = Q @ K^T (3-pass)
        float s[8][4];
        #pragma unroll
        for (int f = 0; f < 8; f++)
            #pragma unroll
            for (int r = 0; r < 4; r++) s[f][r] = 0.f;

        #pragma unroll
        for (int ks = 0; ks < 4; ks++) {
            int kb = ks * 16 + tig * 2;
            #pragma unroll
            for (int nf = 0; nf < 8; nf++) {
                int br = nf * 8 + g;
                uint32_t bh0 = *(const uint32_t*)&sKh[br][kb];
                uint32_t bh1 = *(const uint32_t*)&sKh[br][kb + 8];
                uint32_t bl0 = *(const uint32_t*)&sKl[br][kb];
                uint32_t bl1 = *(const uint32_t*)&sKl[br][kb + 8];
                MMA16816(s[nf], qfh[ks][0], qfh[ks][1], qfh[ks][2], qfh[ks][3], bh0, bh1);
                MMA16816(s[nf], qfh[ks][0], qfh[ks][1], qfh[ks][2], qfh[ks][3], bl0, bl1);
                MMA16816(s[nf], qfl[ks][0], qfl[ks][1], qfl[ks][2], qfl[ks][3], bh0, bh1);
            }
        }

        // rel add + scale + causal mask (clamped indices keep loads in-bounds)
        #pragma unroll
        for (int nf = 0; nf < 8; nf++) {
            int sc = s0 + nf * 8 + tig * 2;
            float r00 = R0[min(sc, rowA)];
            float r01 = R0[min(sc + 1, rowA)];
            float r10 = R1[min(sc, row1)];
            float r11 = R1[min(sc + 1, row1)];
            s[nf][0] = (sc     <= rowA) ? (s[nf][0] + r00) * 0.125f : -1e30f;
            s[nf][1] = (sc + 1 <= rowA) ? (s[nf][1] + r01) * 0.125f : -1e30f;
            s[nf][2] = (sc     <= row1) ? (s[nf][2] + r10) * 0.125f : -1e30f;
            s[nf][3] = (sc + 1 <= row1) ? (s[nf][3] + r11) * 0.125f : -1e30f;
        }

        // online softmax (rows rowA, row1); cols spread over quad (tig)
        float mx0 = -1e30f, mx1 = -1e30f;
        #pragma unroll
        for (int nf = 0; nf < 8; nf++) {
            mx0 = fmaxf(mx0, fmaxf(s[nf][0], s[nf][1]));
            mx1 = fmaxf(mx1, fmaxf(s[nf][2], s[nf][3]));
        }
        mx0 = fmaxf(mx0, __shfl_xor_sync(0xffffffffu, mx0, 1));
        mx0 = fmaxf(mx0, __shfl_xor_sync(0xffffffffu, mx0, 2));
        mx1 = fmaxf(mx1, __shfl_xor_sync(0xffffffffu, mx1, 1));
        mx1 = fmaxf(mx1, __shfl_xor_sync(0xffffffffu, mx1, 2));

        float mn0 = fmaxf(m0, mx0), a0 = __expf(m0 - mn0); m0 = mn0;
        float mn1 = fmaxf(m1, mx1), a1 = __expf(m1 - mn1); m1 = mn1;

        float rs0 = 0.f, rs1 = 0.f;
        #pragma unroll
        for (int nf = 0; nf < 8; nf++) {
            s[nf][0] = __expf(s[nf][0] - mn0);
            s[nf][1] = __expf(s[nf][1] - mn0);
            s[nf][2] = __expf(s[nf][2] - mn1);
            s[nf][3] = __expf(s[nf][3] - mn1);
            rs0 += s[nf][0] + s[nf][1];
            rs1 += s[nf][2] + s[nf][3];
        }
        rs0 += __shfl_xor_sync(0xffffffffu, rs0, 1);
        rs0 += __shfl_xor_sync(0xffffffffu, rs0, 2);
        rs1 += __shfl_xor_sync(0xffffffffu, rs1, 1);
        rs1 += __shfl_xor_sync(0xffffffffu, rs1, 2);
        l0 = l0 * a0 + rs0;
        l1 = l1 * a1 + rs1;
        #pragma unroll
        for (int f = 0; f < 8; f++) {
            o[f][0] *= a0; o[f][1] *= a0;
            o[f][2] *= a1; o[f][3] *= a1;
        }

        // P -> bf16 hi/lo A-fragments (register reuse: c0..c3 == a0..a3)
        uint32_t ph[8][2], pl[8][2];
        #pragma unroll
        for (int f = 0; f < 8; f++) {
            __nv_bfloat16 h00 = __float2bfloat16(s[f][0]);
            __nv_bfloat16 h01 = __float2bfloat16(s[f][1]);
            __nv_bfloat16 h10 = __float2bfloat16(s[f][2]);
            __nv_bfloat16 h11 = __float2bfloat16(s[f][3]);
            ph[f][0] = pack_bf16(h00, h01);
            ph[f][1] = pack_bf16(h10, h11);
            pl[f][0] = pack_f2bf(s[f][0] - __bfloat162float(h00),
                                 s[f][1] - __bfloat162float(h01));
            pl[f][1] = pack_f2bf(s[f][2] - __bfloat162float(h10),
                                 s[f][3] - __bfloat162float(h11));
        }

        // O += P @ V (3-pass); B from transposed V [d][s]
        #pragma unroll
        for (int j = 0; j < 4; j++) {
            uint32_t aH0 = ph[2 * j][0], aH1 = ph[2 * j][1];
            uint32_t aH2 = ph[2 * j + 1][0], aH3 = ph[2 * j + 1][1];
            uint32_t aL0 = pl[2 * j][0], aL1 = pl[2 * j][1];
            uint32_t aL2 = pl[2 * j + 1][0], aL3 = pl[2 * j + 1][1];
            int kb = j * 16 + tig * 2;
            #pragma unroll
            for (int nf = 0; nf < 8; nf++) {
                int vr = nf * 8 + g;
                uint32_t bH0 = *(const uint32_t*)&sVh[vr][kb];
                uint32_t bH1 = *(const uint32_t*)&sVh[vr][kb + 8];
                uint32_t bL0 = *(const uint32_t*)&sVl[vr][kb];
                uint32_t bL1 = *(const uint32_t*)&sVl[vr][kb + 8];
                MMA16816(o[nf], aH0, aH1, aH2, aH3, bH0, bH1);
                MMA16816(o[nf], aH0, aH1, aH2, aH3, bL0, bL1);
                MMA16816(o[nf], aL0, aL1, aL2, aL3, bH0, bH1);
            }
        }
    }

    // epilogue: out[b][t][h*64+d]
    int b = bh >> 4, h = bh & 15;
    float i0 = 1.f / l0, i1 = 1.f / l1;
    #pragma unroll
    for (int nf = 0; nf < 8; nf++) {
        int d = nf * 8 + tig * 2;
        float* op0 = out + ((size_t)b * T_LEN + rowA) * DM + h * DH + d;
        float* op1 = out + ((size_t)b * T_LEN + row1) * DM + h * DH + d;
        *(float2*)op0 = make_float2(o[nf][0] * i0, o[nf][1] * i0);
        *(float2*)op1 = make_float2(o[nf][2] * i1, o[nf][3] * i1);
    }
}

// ---------------------------------------------------------------------------
extern "C" void kernel_launch(void* const* d_in, const int* in_sizes, int n_in,
                              void* d_out, int out_size)
{
    const float* x  = (const float*)d_in[0];
    const float* Wq = (const float*)d_in[1];
    const float* bq = (const float*)d_in[2];
    const float* Wk = (const float*)d_in[3];
    const float* bk = (const float*)d_in[4];
    const float* Wv = (const float*)d_in[5];
    const float* bv = (const float*)d_in[6];
    const float* Er = (const float*)d_in[7];
    float* out = (float*)d_out;

    int NB = in_sizes[0] / (T_LEN * DM);
    if (NB > NB_MAX) NB = NB_MAX;

    // 0) split x / Er, transpose+split W to bf16 hi/lo
    int n4 = NB * T_LEN * DM / 4;
    prep_x<<<(n4 + 255) / 256, 256>>>(x, n4);
    prep_er<<<(T_LEN * DH / 4 + 255) / 256, 256>>>(Er);
    prep_w<<<dim3(32, 32, 3), dim3(32, 8)>>>(Wq, Wk, Wv);

    // 1) q,k,v projections on HMMA (3-pass bf16 split) -> bf16 hi/lo outputs
    dim3 pgrid(8, NB * 8, 3);
    proj_mma<<<pgrid, 256>>>(bq, bk, bv);

    // 2) relative scores R = q @ Er^T (banded) on HMMA
    dim3 rgrid(16, 16, NB * HEADS);
    rel_mma<<<rgrid, 128>>>();

    // 3) flash attention on HMMA
    dim3 agrid(16, NB * HEADS);
    attn_mma<<<agrid, 128>>>(out);
}

// round 9
// speedup vs baseline: 1.9907x; 1.3024x over previous
#include <cuda_runtime.h>
#include <cuda_bf16.h>
#include <cstdint>

// Problem constants (fixed by the reference: N=4, T=1024, H=16, D_HEAD=64)
#define T_LEN 1024
#define HEADS 16
#define DH 64
#define NB_MAX 4
#define DM 1024

// ---------------------------------------------------------------------------
// Scratch (device globals — no allocation allowed in kernel_launch)
// ---------------------------------------------------------------------------
__device__ __align__(16) float g_R[(size_t)NB_MAX * HEADS * T_LEN * T_LEN]; // [bh][t][c], c=s-t+1023
__device__ __align__(16) __nv_bfloat16 g_xh[NB_MAX * T_LEN * DM];
__device__ __align__(16) __nv_bfloat16 g_xl[NB_MAX * T_LEN * DM];
__device__ __align__(16) __nv_bfloat16 g_wth[3 * DM * DM];  // W^T [mat][n][k]
__device__ __align__(16) __nv_bfloat16 g_wtl[3 * DM * DM];
__device__ __align__(16) __nv_bfloat16 g_qh[NB_MAX * HEADS * T_LEN * DH];
__device__ __align__(16) __nv_bfloat16 g_ql[NB_MAX * HEADS * T_LEN * DH];
__device__ __align__(16) __nv_bfloat16 g_kh[NB_MAX * HEADS * T_LEN * DH];
__device__ __align__(16) __nv_bfloat16 g_kl[NB_MAX * HEADS * T_LEN * DH];
__device__ __align__(16) __nv_bfloat16 g_vh[NB_MAX * HEADS * T_LEN * DH];
__device__ __align__(16) __nv_bfloat16 g_vl[NB_MAX * HEADS * T_LEN * DH];
__device__ __align__(16) __nv_bfloat16 g_erh[T_LEN * DH];
__device__ __align__(16) __nv_bfloat16 g_erl[T_LEN * DH];

// mma.sync m16n8k16 row.col f32.bf16.bf16.f32 (base PTX — works on sm_100)
#define MMA16816(d, a0, a1, a2, a3, b0, b1)                                   \
    asm volatile(                                                             \
        "mma.sync.aligned.m16n8k16.row.col.f32.bf16.bf16.f32 "                \
        "{%0,%1,%2,%3}, {%4,%5,%6,%7}, {%8,%9}, {%0,%1,%2,%3};"               \
        : "+f"((d)[0]), "+f"((d)[1]), "+f"((d)[2]), "+f"((d)[3])              \
        : "r"(a0), "r"(a1), "r"(a2), "r"(a3), "r"(b0), "r"(b1))

#define LDMX4(r0, r1, r2, r3, a)                                              \
    asm volatile("ldmatrix.sync.aligned.m8n8.x4.shared.b16 {%0,%1,%2,%3}, [%4];" \
                 : "=r"(r0), "=r"(r1), "=r"(r2), "=r"(r3) : "r"(a))
#define LDMX2(r0, r1, a)                                                      \
    asm volatile("ldmatrix.sync.aligned.m8n8.x2.shared.b16 {%0,%1}, [%2];"    \
                 : "=r"(r0), "=r"(r1) : "r"(a))
#define LDMX2T(r0, r1, a)                                                     \
    asm volatile("ldmatrix.sync.aligned.m8n8.x2.trans.shared.b16 {%0,%1}, [%2];" \
                 : "=r"(r0), "=r"(r1) : "r"(a))
#define CP16(dst_u32, src)                                                    \
    asm volatile("cp.async.cg.shared.global [%0], [%1], 16;"                  \
                 :: "r"(dst_u32), "l"(src))
#define CP_COMMIT() asm volatile("cp.async.commit_group;" ::: "memory")
#define CP_WAIT(n)  asm volatile("cp.async.wait_group %0;" :: "n"(n) : "memory")

__device__ __forceinline__ uint32_t smem_u32(const void* p) {
    uint32_t a;
    asm("{ .reg .u64 t; cvta.to.shared.u64 t, %1; cvt.u32.u64 %0, t; }"
        : "=r"(a) : "l"(p));
    return a;
}
__device__ __forceinline__ uint32_t pack_bf16(__nv_bfloat16 a, __nv_bfloat16 b) {
    __nv_bfloat162 t = __halves2bfloat162(a, b);
    return *(uint32_t*)&t;
}
__device__ __forceinline__ uint32_t pack_f2bf(float a, float b) {
    __nv_bfloat162 t = __floats2bfloat162_rn(a, b);
    return *(uint32_t*)&t;
}

// ---------------------------------------------------------------------------
// prep kernels: fp32 -> bf16 hi/lo splits (x, Er), W transpose+split
// ---------------------------------------------------------------------------
__global__ __launch_bounds__(256) void prep_x(const float* __restrict__ x, int n4)
{
    int i = blockIdx.x * 256 + threadIdx.x;
    if (i >= n4) return;
    float4 v = ((const float4*)x)[i];
    __nv_bfloat16 h[4], l[4];
    float f[4] = {v.x, v.y, v.z, v.w};
    #pragma unroll
    for (int j = 0; j < 4; j++) {
        h[j] = __float2bfloat16(f[j]);
        l[j] = __float2bfloat16(f[j] - __bfloat162float(h[j]));
    }
    __nv_bfloat162* oh = (__nv_bfloat162*)g_xh;
    __nv_bfloat162* ol = (__nv_bfloat162*)g_xl;
    oh[2 * i]     = __halves2bfloat162(h[0], h[1]);
    oh[2 * i + 1] = __halves2bfloat162(h[2], h[3]);
    ol[2 * i]     = __halves2bfloat162(l[0], l[1]);
    ol[2 * i + 1] = __halves2bfloat162(l[2], l[3]);
}

__global__ __launch_bounds__(256) void prep_er(const float* __restrict__ er)
{
    int i = blockIdx.x * 256 + threadIdx.x;
    if (i >= T_LEN * DH / 4) return;
    float4 v = ((const float4*)er)[i];
    float f[4] = {v.x, v.y, v.z, v.w};
    __nv_bfloat16 h[4], l[4];
    #pragma unroll
    for (int j = 0; j < 4; j++) {
        h[j] = __float2bfloat16(f[j]);
        l[j] = __float2bfloat16(f[j] - __bfloat162float(h[j]));
    }
    __nv_bfloat162* oh = (__nv_bfloat162*)g_erh;
    __nv_bfloat162* ol = (__nv_bfloat162*)g_erl;
    oh[2 * i]     = __halves2bfloat162(h[0], h[1]);
    oh[2 * i + 1] = __halves2bfloat162(h[2], h[3]);
    ol[2 * i]     = __halves2bfloat162(l[0], l[1]);
    ol[2 * i + 1] = __halves2bfloat162(l[2], l[3]);
}

__global__ __launch_bounds__(256) void prep_w(const float* __restrict__ Wq,
                                              const float* __restrict__ Wk,
                                              const float* __restrict__ Wv)
{
    const float* W = (blockIdx.z == 0) ? Wq : (blockIdx.z == 1) ? Wk : Wv;
    __shared__ float t[32][33];
    int tx = threadIdx.x, ty = threadIdx.y;        // 32 x 8
    int n0 = blockIdx.x * 32, k0 = blockIdx.y * 32;
    #pragma unroll
    for (int i = 0; i < 4; i++)
        t[ty + 8 * i][tx] = W[(size_t)(k0 + ty + 8 * i) * DM + n0 + tx];
    __syncthreads();
    __nv_bfloat16* oh = g_wth + (size_t)blockIdx.z * DM * DM;
    __nv_bfloat16* ol = g_wtl + (size_t)blockIdx.z * DM * DM;
    #pragma unroll
    for (int i = 0; i < 4; i++) {
        int n = n0 + ty + 8 * i;
        float v = t[tx][ty + 8 * i];
        __nv_bfloat16 h = __float2bfloat16(v);
        oh[(size_t)n * DM + k0 + tx] = h;
        ol[(size_t)n * DM + k0 + tx] = __float2bfloat16(v - __bfloat162float(h));
    }
}

// ---------------------------------------------------------------------------
// proj_mma: 128x128 tile, 3-pass bf16 hi/lo HMMA, cp.async 2-stage pipeline,
// ldmatrix fragment loads, 2 CTAs/SM.
// ---------------------------------------------------------------------------
#define KC 32
#define NCHUNK (DM / KC)            // 32
#define SPAD 40                     // smem row stride in bf16 (80 B)
#define ARR_B (128 * SPAD * 2)      // 10240 bytes per array
#define STAGE_B (4 * ARR_B)         // 40960
#define PROJ_SMEM (2 * STAGE_B)     // 81920

__global__ __launch_bounds__(256, 2) void proj_mma(const float* __restrict__ bq,
                                                   const float* __restrict__ bk,
                                                   const float* __restrict__ bv)
{
    extern __shared__ char sm[];
    uint32_t smb = smem_u32(sm);

    int tid = threadIdx.x;
    int wid = tid >> 5, lane = tid & 31;
    int g = lane >> 2, tig = lane & 3;
    int l15 = lane & 15;
    int wm = wid >> 2, wn = wid & 3;             // 2 x 4 warp grid
    int n0 = blockIdx.x * 128;
    int m0 = blockIdx.y * 128;
    int mat = blockIdx.z;

    const float* bias = (mat == 0) ? bq : (mat == 1) ? bk : bv;
    __nv_bfloat16* outh = (mat == 0) ? g_qh : (mat == 1) ? g_kh : g_vh;
    __nv_bfloat16* outl = (mat == 0) ? g_ql : (mat == 1) ? g_kl : g_vl;
    const __nv_bfloat16* ah = g_xh + (size_t)m0 * DM;
    const __nv_bfloat16* al = g_xl + (size_t)m0 * DM;
    const __nv_bfloat16* bh = g_wth + (size_t)mat * DM * DM + (size_t)n0 * DM;
    const __nv_bfloat16* bl = g_wtl + (size_t)mat * DM * DM + (size_t)n0 * DM;

    float acc[4][4][4];
    #pragma unroll
    for (int i = 0; i < 4; i++)
        #pragma unroll
        for (int j = 0; j < 4; j++)
            #pragma unroll
            for (int r = 0; r < 4; r++) acc[i][j][r] = 0.f;

    // cp.async source/dst mapping: thread covers rows r0, r0+64, 16B each
    int r0 = tid >> 2, c0 = (tid & 3) * 8;           // row, bf16-col
    uint32_t dOff0 = (uint32_t)(r0 * 80 + c0 * 2);
    uint32_t dOff1 = dOff0 + 64 * 80;
    const __nv_bfloat16* srcs[4] = {ah, al, bh, bl};

    // ldmatrix per-lane offsets
    // A (x4): rowsel = (lane&7) + ((lane>>3)&1)*8 ; colsel = (lane>>4)*8
    uint32_t aOff = (uint32_t)(((wm * 64) + (lane & 7) + ((lane >> 3) & 1) * 8) * 80
                               + (lane >> 4) * 16);
    // B (x2): rows wn*32 + (l15&7); colsel = (l15>>3)*8
    uint32_t bOff = (uint32_t)(((wn * 32) + (l15 & 7)) * 80 + (l15 >> 3) * 16);

    // issue chunk k0 into stage st
    auto issue = [&](int c) {
        uint32_t sb = smb + (uint32_t)(c & 1) * STAGE_B;
        int k0 = c * KC;
        #pragma unroll
        for (int a = 0; a < 4; a++) {
            const __nv_bfloat16* s = srcs[a] + k0;
            uint32_t d = sb + (uint32_t)a * ARR_B;
            CP16(d + dOff0, s + (size_t)r0 * DM + c0);
            CP16(d + dOff1, s + (size_t)(r0 + 64) * DM + c0);
        }
        CP_COMMIT();
    };

    issue(0);

    #pragma unroll 1
    for (int c = 0; c < NCHUNK; c++) {
        if (c + 1 < NCHUNK) { issue(c + 1); CP_WAIT(1); }
        else                { CP_WAIT(0); }
        __syncthreads();

        uint32_t sb = smb + (uint32_t)(c & 1) * STAGE_B;
        uint32_t aH = sb + aOff;
        uint32_t aL = sb + ARR_B + aOff;
        uint32_t bH = sb + 2 * ARR_B + bOff;
        uint32_t bL = sb + 3 * ARR_B + bOff;

        #pragma unroll
        for (int kk = 0; kk < 2; kk++) {
            uint32_t kb = (uint32_t)kk * 32;   // 16 cols * 2B
            uint32_t vbh[4][2], vbl[4][2];
            #pragma unroll
            for (int nf = 0; nf < 4; nf++) {
                LDMX2(vbh[nf][0], vbh[nf][1], bH + (uint32_t)nf * 640 + kb);
                LDMX2(vbl[nf][0], vbl[nf][1], bL + (uint32_t)nf * 640 + kb);
            }
            #pragma unroll
            for (int mf = 0; mf < 4; mf++) {
                uint32_t a0, a1, a2, a3, b0, b1, b2, b3;
                LDMX4(a0, a1, a2, a3, aH + (uint32_t)mf * 1280 + kb);
                LDMX4(b0, b1, b2, b3, aL + (uint32_t)mf * 1280 + kb);
                #pragma unroll
                for (int nf = 0; nf < 4; nf++) {
                    MMA16816(acc[mf][nf], a0, a1, a2, a3, vbh[nf][0], vbh[nf][1]);
                    MMA16816(acc[mf][nf], a0, a1, a2, a3, vbl[nf][0], vbl[nf][1]);
                    MMA16816(acc[mf][nf], b0, b1, b2, b3, vbh[nf][0], vbh[nf][1]);
                }
            }
        }
        __syncthreads();
    }

    // Epilogue: bias + split to bf16 hi/lo + scatter to [b,h,t,d]
    #pragma unroll
    for (int mf = 0; mf < 4; mf++) {
        #pragma unroll
        for (int nf = 0; nf < 4; nf++) {
            int n = n0 + wn * 32 + nf * 8 + tig * 2;
            int h = n >> 6, d = n & 63;
            float b0 = bias[n], b1 = bias[n + 1];
            #pragma unroll
            for (int half = 0; half < 2; half++) {
                int m = m0 + wm * 64 + mf * 16 + g + half * 8;
                int b = m >> 10, t = m & 1023;
                size_t idx = (((size_t)b * HEADS + h) * T_LEN + t) * DH + d;
                float v0 = acc[mf][nf][half * 2] + b0;
                float v1 = acc[mf][nf][half * 2 + 1] + b1;
                __nv_bfloat16 h0 = __float2bfloat16(v0);
                __nv_bfloat16 h1 = __float2bfloat16(v1);
                *(uint32_t*)&outh[idx] = pack_bf16(h0, h1);
                *(uint32_t*)&outl[idx] = pack_f2bf(v0 - __bfloat162float(h0),
                                                   v1 - __bfloat162float(h1));
            }
        }
    }
}

// ---------------------------------------------------------------------------
// rel_mma: banded R[bh][t][c] = q[bh][t].Er[c] on HMMA (3-pass hi/lo).
// Er B-fragments via ldmatrix.x2. 128 thr, 64x64 tile.
// ---------------------------------------------------------------------------
#define EPAD 72
#define EROW (EPAD * 2)   // 144 bytes

__global__ __launch_bounds__(128) void rel_mma()
{
    __shared__ __nv_bfloat16 sEh[64][EPAD];
    __shared__ __nv_bfloat16 sEl[64][EPAD];

    int sb = blockIdx.x, tb = blockIdx.y, bh = blockIdx.z;
    if (tb + sb < 15) return;   // tile never read under causal mask

    int tid = threadIdx.x, w = tid >> 5, lane = tid & 31;
    int l15 = lane & 15;
    int t0 = tb * 64, s0 = sb * 64;

    const __nv_bfloat16* qh = g_qh + (size_t)bh * T_LEN * DH;
    const __nv_bfloat16* ql = g_ql + (size_t)bh * T_LEN * DH;

    for (int i = tid; i < 512; i += 128) {
        int r = i >> 3, c = (i & 7) * 8;
        *(uint4*)&sEh[r][c] = *(const uint4*)&g_erh[(s0 + r) * DH + c];
        *(uint4*)&sEl[r][c] = *(const uint4*)&g_erl[(s0 + r) * DH + c];
    }

    int rowA = t0 + w * 16 + (lane >> 2);
    int tig = lane & 3;
    uint32_t qfh[4][4], qfl[4][4];
    #pragma unroll
    for (int ks = 0; ks < 4; ks++) {
        int d0 = ks * 16 + tig * 2;
        qfh[ks][0] = *(const uint32_t*)&qh[(size_t)rowA * DH + d0];
        qfh[ks][1] = *(const uint32_t*)&qh[(size_t)(rowA + 8) * DH + d0];
        qfh[ks][2] = *(const uint32_t*)&qh[(size_t)rowA * DH + d0 + 8];
        qfh[ks][3] = *(const uint32_t*)&qh[(size_t)(rowA + 8) * DH + d0 + 8];
        qfl[ks][0] = *(const uint32_t*)&ql[(size_t)rowA * DH + d0];
        qfl[ks][1] = *(const uint32_t*)&ql[(size_t)(rowA + 8) * DH + d0];
        qfl[ks][2] = *(const uint32_t*)&ql[(size_t)rowA * DH + d0 + 8];
        qfl[ks][3] = *(const uint32_t*)&ql[(size_t)(rowA + 8) * DH + d0 + 8];
    }
    __syncthreads();

    float acc[8][4];
    #pragma unroll
    for (int f = 0; f < 8; f++)
        #pragma unroll
        for (int r = 0; r < 4; r++) acc[f][r] = 0.f;

    uint32_t eOff = (uint32_t)((l15 & 7) * EROW + (l15 >> 3) * 16);
    uint32_t eH = smem_u32(&sEh[0][0]) + eOff;
    uint32_t eL = smem_u32(&sEl[0][0]) + eOff;

    #pragma unroll
    for (int ks = 0; ks < 4; ks++) {
        uint32_t kb = (uint32_t)ks * 32;
        #pragma unroll
        for (int nf = 0; nf < 8; nf++) {
            uint32_t b0, b1, c0, c1;
            LDMX2(b0, b1, eH + (uint32_t)nf * 8 * EROW + kb);
            LDMX2(c0, c1, eL + (uint32_t)nf * 8 * EROW + kb);
            MMA16816(acc[nf], qfh[ks][0], qfh[ks][1], qfh[ks][2], qfh[ks][3], b0, b1);
            MMA16816(acc[nf], qfh[ks][0], qfh[ks][1], qfh[ks][2], qfh[ks][3], c0, c1);
            MMA16816(acc[nf], qfl[ks][0], qfl[ks][1], qfl[ks][2], qfl[ks][3], b0, b1);
        }
    }

    float* Rg = g_R + (size_t)bh * T_LEN * T_LEN;
    #pragma unroll
    for (int nf = 0; nf < 8; nf++) {
        int c = s0 + nf * 8 + tig * 2;
        *(float2*)&Rg[(size_t)rowA * T_LEN + c] = make_float2(acc[nf][0], acc[nf][1]);
        *(float2*)&Rg[(size_t)(rowA + 8) * T_LEN + c] = make_float2(acc[nf][2], acc[nf][3]);
    }
}

// ---------------------------------------------------------------------------
// attn_mma: FA2 flash attention on HMMA (3-pass hi/lo). K natural + ldmatrix,
// V natural + ldmatrix.trans (no explicit transpose). 128 thr, 64-row t-tile.
// ---------------------------------------------------------------------------
__global__ __launch_bounds__(128) void attn_mma(float* __restrict__ out)
{
    __shared__ __nv_bfloat16 sKh[64][EPAD];
    __shared__ __nv_bfloat16 sKl[64][EPAD];
    __shared__ __nv_bfloat16 sVh[64][EPAD];   // natural [s][d]
    __shared__ __nv_bfloat16 sVl[64][EPAD];

    int tid = threadIdx.x, w = tid >> 5, lane = tid & 31;
    int g = lane >> 2, tig = lane & 3;
    int l15 = lane & 15;
    int tb = blockIdx.x, bh = blockIdx.y;
    int t0 = tb * 64;

    const __nv_bfloat16* qh = g_qh + (size_t)bh * T_LEN * DH;
    const __nv_bfloat16* ql = g_ql + (size_t)bh * T_LEN * DH;
    const __nv_bfloat16* kh = g_kh + (size_t)bh * T_LEN * DH;
    const __nv_bfloat16* kl = g_kl + (size_t)bh * T_LEN * DH;
    const __nv_bfloat16* vh = g_vh + (size_t)bh * T_LEN * DH;
    const __nv_bfloat16* vl = g_vl + (size_t)bh * T_LEN * DH;
    const float* Rg = g_R + (size_t)bh * T_LEN * T_LEN;

    int rowA = t0 + w * 16 + g;
    int row1 = rowA + 8;

    uint32_t qfh[4][4], qfl[4][4];
    #pragma unroll
    for (int ks = 0; ks < 4; ks++) {
        int d0 = ks * 16 + tig * 2;
        qfh[ks][0] = *(const uint32_t*)&qh[(size_t)rowA * DH + d0];
        qfh[ks][1] = *(const uint32_t*)&qh[(size_t)row1 * DH + d0];
        qfh[ks][2] = *(const uint32_t*)&qh[(size_t)rowA * DH + d0 + 8];
        qfh[ks][3] = *(const uint32_t*)&qh[(size_t)row1 * DH + d0 + 8];
        qfl[ks][0] = *(const uint32_t*)&ql[(size_t)rowA * DH + d0];
        qfl[ks][1] = *(const uint32_t*)&ql[(size_t)row1 * DH + d0];
        qfl[ks][2] = *(const uint32_t*)&ql[(size_t)rowA * DH + d0 + 8];
        qfl[ks][3] = *(const uint32_t*)&ql[(size_t)row1 * DH + d0 + 8];
    }

    float m0 = -1e30f, m1 = -1e30f, l0 = 0.f, l1 = 0.f;
    float o[8][4];
    #pragma unroll
    for (int f = 0; f < 8; f++)
        #pragma unroll
        for (int r = 0; r < 4; r++) o[f][r] = 0.f;

    const float* R0 = Rg + (size_t)rowA * T_LEN + (T_LEN - 1 - rowA);
    const float* R1 = Rg + (size_t)row1 * T_LEN + (T_LEN - 1 - row1);

    // ldmatrix per-lane offsets
    uint32_t kOff = (uint32_t)((l15 & 7) * EROW + (l15 >> 3) * 16);
    uint32_t kBH = smem_u32(&sKh[0][0]) + kOff;
    uint32_t kBL = smem_u32(&sKl[0][0]) + kOff;
    uint32_t vOff = (uint32_t)(((l15 & 7) + (l15 >> 3) * 8) * EROW);
    uint32_t vBH = smem_u32(&sVh[0][0]) + vOff;
    uint32_t vBL = smem_u32(&sVl[0][0]) + vOff;

    #pragma unroll 1
    for (int sb = 0; sb <= tb; sb++) {
        int s0 = sb * 64;
        __syncthreads();
        for (int i = tid; i < 512; i += 128) {
            int r = i >> 3, c = (i & 7) * 8;
            *(uint4*)&sKh[r][c] = *(const uint4*)&kh[(size_t)(s0 + r) * DH + c];
            *(uint4*)&sKl[r][c] = *(const uint4*)&kl[(size_t)(s0 + r) * DH + c];
            *(uint4*)&sVh[r][c] = *(const uint4*)&vh[(size_t)(s0 + r) * DH + c];
            *(uint4*)&sVl[r][c] = *(const uint4*)&vl[(size_t)(s0 + r) * DH + c];
        }
        __syncthreads();

        // S = Q @ K^T (3-pass)
        float s[8][4];
        #pragma unroll
        for (int f = 0; f < 8; f++)
            #pragma unroll
            for (int r = 0; r < 4; r++) s[f][r] = 0.f;

        #pragma unroll
        for (int ks = 0; ks < 4; ks++) {
            uint32_t kb = (uint32_t)ks * 32;
            #pragma unroll
            for (int nf = 0; nf < 8; nf++) {
                uint32_t b0, b1, c0, c1;
                LDMX2(b0, b1, kBH + (uint32_t)nf * 8 * EROW + kb);
                LDMX2(c0, c1, kBL + (uint32_t)nf * 8 * EROW + kb);
                MMA16816(s[nf], qfh[ks][0], qfh[ks][1], qfh[ks][2], qfh[ks][3], b0, b1);
                MMA16816(s[nf], qfh[ks][0], qfh[ks][1], qfh[ks][2], qfh[ks][3], c0, c1);
                MMA16816(s[nf], qfl[ks][0], qfl[ks][1], qfl[ks][2], qfl[ks][3], b0, b1);
            }
        }

        // rel add + scale + causal mask (clamped indices keep loads in-bounds)
        #pragma unroll
        for (int nf = 0; nf < 8; nf++) {
            int sc = s0 + nf * 8 + tig * 2;
            float r00 = R0[min(sc, rowA)];
            float r01 = R0[min(sc + 1, rowA)];
            float r10 = R1[min(sc, row1)];
            float r11 = R1[min(sc + 1, row1)];
            s[nf][0] = (sc     <= rowA) ? (s[nf][0] + r00) * 0.125f : -1e30f;
            s[nf][1] = (sc + 1 <= rowA) ? (s[nf][1] + r01) * 0.125f : -1e30f;
            s[nf][2] = (sc     <= row1) ? (s[nf][2] + r10) * 0.125f : -1e30f;
            s[nf][3] = (sc + 1 <= row1) ? (s[nf][3] + r11) * 0.125f : -1e30f;
        }

        // online softmax
        float mx0 = -1e30f, mx1 = -1e30f;
        #pragma unroll
        for (int nf = 0; nf < 8; nf++) {
            mx0 = fmaxf(mx0, fmaxf(s[nf][0], s[nf][1]));
            mx1 = fmaxf(mx1, fmaxf(s[nf][2], s[nf][3]));
        }
        mx0 = fmaxf(mx0, __shfl_xor_sync(0xffffffffu, mx0, 1));
        mx0 = fmaxf(mx0, __shfl_xor_sync(0xffffffffu, mx0, 2));
        mx1 = fmaxf(mx1, __shfl_xor_sync(0xffffffffu, mx1, 1));
        mx1 = fmaxf(mx1, __shfl_xor_sync(0xffffffffu, mx1, 2));

        float mn0 = fmaxf(m0, mx0), a0 = __expf(m0 - mn0); m0 = mn0;
        float mn1 = fmaxf(m1, mx1), a1 = __expf(m1 - mn1); m1 = mn1;

        float rs0 = 0.f, rs1 = 0.f;
        #pragma unroll
        for (int nf = 0; nf < 8; nf++) {
            s[nf][0] = __expf(s[nf][0] - mn0);
            s[nf][1] = __expf(s[nf][1] - mn0);
            s[nf][2] = __expf(s[nf][2] - mn1);
            s[nf][3] = __expf(s[nf][3] - mn1);
            rs0 += s[nf][0] + s[nf][1];
            rs1 += s[nf][2] + s[nf][3];
        }
        rs0 += __shfl_xor_sync(0xffffffffu, rs0, 1);
        rs0 += __shfl_xor_sync(0xffffffffu, rs0, 2);
        rs1 += __shfl_xor_sync(0xffffffffu, rs1, 1);
        rs1 += __shfl_xor_sync(0xffffffffu, rs1, 2);
        l0 = l0 * a0 + rs0;
        l1 = l1 * a1 + rs1;
        #pragma unroll
        for (int f = 0; f < 8; f++) {
            o[f][0] *= a0; o[f][1] *= a0;
            o[f][2] *= a1; o[f][3] *= a1;
        }

        // P -> bf16 hi/lo A-fragments
        uint32_t ph[8][2], pl[8][2];
        #pragma unroll
        for (int f = 0; f < 8; f++) {
            __nv_bfloat16 h00 = __float2bfloat16(s[f][0]);
            __nv_bfloat16 h01 = __float2bfloat16(s[f][1]);
            __nv_bfloat16 h10 = __float2bfloat16(s[f][2]);
            __nv_bfloat16 h11 = __float2bfloat16(s[f][3]);
            ph[f][0] = pack_bf16(h00, h01);
            ph[f][1] = pack_bf16(h10, h11);
            pl[f][0] = pack_f2bf(s[f][0] - __bfloat162float(h00),
                                 s[f][1] - __bfloat162float(h01));
            pl[f][1] = pack_f2bf(s[f][2] - __bfloat162float(h10),
                                 s[f][3] - __bfloat162float(h11));
        }

        // O += P @ V (3-pass); V B-frags via ldmatrix.trans from natural [s][d]
        #pragma unroll
        for (int j = 0; j < 4; j++) {
            uint32_t aH0 = ph[2 * j][0], aH1 = ph[2 * j][1];
            uint32_t aH2 = ph[2 * j + 1][0], aH3 = ph[2 * j + 1][1];
            uint32_t aL0 = pl[2 * j][0], aL1 = pl[2 * j][1];
            uint32_t aL2 = pl[2 * j + 1][0], aL3 = pl[2 * j + 1][1];
            uint32_t jrow = (uint32_t)(j * 16) * EROW;
            #pragma unroll
            for (int nf = 0; nf < 8; nf++) {
                uint32_t bH0, bH1, bL0, bL1;
                LDMX2T(bH0, bH1, vBH + jrow + (uint32_t)nf * 16);
                LDMX2T(bL0, bL1, vBL + jrow + (uint32_t)nf * 16);
                MMA16816(o[nf], aH0, aH1, aH2, aH3, bH0, bH1);
                MMA16816(o[nf], aH0, aH1, aH2, aH3, bL0, bL1);
                MMA16816(o[nf], aL0, aL1, aL2, aL3, bH0, bH1);
            }
        }
    }

    // epilogue: out[b][t][h*64+d]
    int b = bh >> 4, h = bh & 15;
    float i0 = 1.f / l0, i1 = 1.f / l1;
    #pragma unroll
    for (int nf = 0; nf < 8; nf++) {
        int d = nf * 8 + tig * 2;
        float* op0 = out + ((size_t)b * T_LEN + rowA) * DM + h * DH + d;
        float* op1 = out + ((size_t)b * T_LEN + row1) * DM + h * DH + d;
        *(float2*)op0 = make_float2(o[nf][0] * i0, o[nf][1] * i0);
        *(float2*)op1 = make_float2(o[nf][2] * i1, o[nf][3] * i1);
    }
}

// ---------------------------------------------------------------------------
extern "C" void kernel_launch(void* const* d_in, const int* in_sizes, int n_in,
                              void* d_out, int out_size)
{
    const float* x  = (const float*)d_in[0];
    const float* Wq = (const float*)d_in[1];
    const float* bq = (const float*)d_in[2];
    const float* Wk = (const float*)d_in[3];
    const float* bk = (const float*)d_in[4];
    const float* Wv = (const float*)d_in[5];
    const float* bv = (const float*)d_in[6];
    const float* Er = (const float*)d_in[7];
    float* out = (float*)d_out;

    int NB = in_sizes[0] / (T_LEN * DM);
    if (NB > NB_MAX) NB = NB_MAX;

    cudaFuncSetAttribute(proj_mma, cudaFuncAttributeMaxDynamicSharedMemorySize,
                         PROJ_SMEM);

    // 0) split x / Er, transpose+split W to bf16 hi/lo
    int n4 = NB * T_LEN * DM / 4;
    prep_x<<<(n4 + 255) / 256, 256>>>(x, n4);
    prep_er<<<(T_LEN * DH / 4 + 255) / 256, 256>>>(Er);
    prep_w<<<dim3(32, 32, 3), dim3(32, 8)>>>(Wq, Wk, Wv);

    // 1) q,k,v projections on HMMA (cp.async pipeline, ldmatrix)
    dim3 pgrid(8, NB * 8, 3);
    proj_mma<<<pgrid, 256, PROJ_SMEM>>>(bq, bk, bv);

    // 2) relative scores R = q @ Er^T (banded) on HMMA
    dim3 rgrid(16, 16, NB * HEADS);
    rel_mma<<<rgrid, 128>>>();

    // 3) flash attention on HMMA
    dim3 agrid(16, NB * HEADS);
    attn_mma<<<agrid, 128>>>(out);
}

// round 11
// speedup vs baseline: 2.3211x; 1.1660x over previous
#include <cuda_runtime.h>
#include <cuda_bf16.h>
#include <cstdint>

// Problem constants (fixed by the reference: N=4, T=1024, H=16, D_HEAD=64)
#define T_LEN 1024
#define HEADS 16
#define DH 64
#define NB_MAX 4
#define DM 1024

// ---------------------------------------------------------------------------
// Scratch (device globals — no allocation allowed in kernel_launch)
// ---------------------------------------------------------------------------
__device__ __align__(16) float g_R[(size_t)NB_MAX * HEADS * T_LEN * T_LEN]; // [bh][t][c], c=s-t+1023
__device__ __align__(16) __nv_bfloat16 g_xh[NB_MAX * T_LEN * DM];
__device__ __align__(16) __nv_bfloat16 g_xl[NB_MAX * T_LEN * DM];
__device__ __align__(16) __nv_bfloat16 g_wth[3 * DM * DM];  // W^T [mat][n][k]
__device__ __align__(16) __nv_bfloat16 g_wtl[3 * DM * DM];
__device__ __align__(16) __nv_bfloat16 g_qh[NB_MAX * HEADS * T_LEN * DH];
__device__ __align__(16) __nv_bfloat16 g_ql[NB_MAX * HEADS * T_LEN * DH];
__device__ __align__(16) __nv_bfloat16 g_kh[NB_MAX * HEADS * T_LEN * DH];
__device__ __align__(16) __nv_bfloat16 g_kl[NB_MAX * HEADS * T_LEN * DH];
__device__ __align__(16) __nv_bfloat16 g_vh[NB_MAX * HEADS * T_LEN * DH];
__device__ __align__(16) __nv_bfloat16 g_vl[NB_MAX * HEADS * T_LEN * DH];
__device__ __align__(16) __nv_bfloat16 g_erh[T_LEN * DH];
__device__ __align__(16) __nv_bfloat16 g_erl[T_LEN * DH];

// mma.sync m16n8k16 row.col f32.bf16.bf16.f32 (base PTX — works on sm_100)
#define MMA16816(d, a0, a1, a2, a3, b0, b1)                                   \
    asm volatile(                                                             \
        "mma.sync.aligned.m16n8k16.row.col.f32.bf16.bf16.f32 "                \
        "{%0,%1,%2,%3}, {%4,%5,%6,%7}, {%8,%9}, {%0,%1,%2,%3};"               \
        : "+f"((d)[0]), "+f"((d)[1]), "+f"((d)[2]), "+f"((d)[3])              \
        : "r"(a0), "r"(a1), "r"(a2), "r"(a3), "r"(b0), "r"(b1))

#define LDMX4(r0, r1, r2, r3, a)                                              \
    asm volatile("ldmatrix.sync.aligned.m8n8.x4.shared.b16 {%0,%1,%2,%3}, [%4];" \
                 : "=r"(r0), "=r"(r1), "=r"(r2), "=r"(r3) : "r"(a))
#define LDMX2(r0, r1, a)                                                      \
    asm volatile("ldmatrix.sync.aligned.m8n8.x2.shared.b16 {%0,%1}, [%2];"    \
                 : "=r"(r0), "=r"(r1) : "r"(a))
#define LDMX2T(r0, r1, a)                                                     \
    asm volatile("ldmatrix.sync.aligned.m8n8.x2.trans.shared.b16 {%0,%1}, [%2];" \
                 : "=r"(r0), "=r"(r1) : "r"(a))
#define CP16(dst_u32, src)                                                    \
    asm volatile("cp.async.cg.shared.global [%0], [%1], 16;"                  \
                 :: "r"(dst_u32), "l"(src))
#define CP_COMMIT() asm volatile("cp.async.commit_group;" ::: "memory")
#define CP_WAIT(n)  asm volatile("cp.async.wait_group %0;" :: "n"(n) : "memory")

__device__ __forceinline__ uint32_t smem_u32(const void* p) {
    uint32_t a;
    asm("{ .reg .u64 t; cvta.to.shared.u64 t, %1; cvt.u32.u64 %0, t; }"
        : "=r"(a) : "l"(p));
    return a;
}
__device__ __forceinline__ uint32_t pack_bf16(__nv_bfloat16 a, __nv_bfloat16 b) {
    __nv_bfloat162 t = __halves2bfloat162(a, b);
    return *(uint32_t*)&t;
}
__device__ __forceinline__ uint32_t pack_f2bf(float a, float b) {
    __nv_bfloat162 t = __floats2bfloat162_rn(a, b);
    return *(uint32_t*)&t;
}

// ---------------------------------------------------------------------------
// prep kernels: fp32 -> bf16 hi/lo splits (x, Er), W transpose+split
// ---------------------------------------------------------------------------
__global__ __launch_bounds__(256) void prep_x(const float* __restrict__ x, int n4)
{
    int i = blockIdx.x * 256 + threadIdx.x;
    if (i >= n4) return;
    float4 v = ((const float4*)x)[i];
    __nv_bfloat16 h[4], l[4];
    float f[4] = {v.x, v.y, v.z, v.w};
    #pragma unroll
    for (int j = 0; j < 4; j++) {
        h[j] = __float2bfloat16(f[j]);
        l[j] = __float2bfloat16(f[j] - __bfloat162float(h[j]));
    }
    __nv_bfloat162* oh = (__nv_bfloat162*)g_xh;
    __nv_bfloat162* ol = (__nv_bfloat162*)g_xl;
    oh[2 * i]     = __halves2bfloat162(h[0], h[1]);
    oh[2 * i + 1] = __halves2bfloat162(h[2], h[3]);
    ol[2 * i]     = __halves2bfloat162(l[0], l[1]);
    ol[2 * i + 1] = __halves2bfloat162(l[2], l[3]);
}

__global__ __launch_bounds__(256) void prep_er(const float* __restrict__ er)
{
    int i = blockIdx.x * 256 + threadIdx.x;
    if (i >= T_LEN * DH / 4) return;
    float4 v = ((const float4*)er)[i];
    float f[4] = {v.x, v.y, v.z, v.w};
    __nv_bfloat16 h[4], l[4];
    #pragma unroll
    for (int j = 0; j < 4; j++) {
        h[j] = __float2bfloat16(f[j]);
        l[j] = __float2bfloat16(f[j] - __bfloat162float(h[j]));
    }
    __nv_bfloat162* oh = (__nv_bfloat162*)g_erh;
    __nv_bfloat162* ol = (__nv_bfloat162*)g_erl;
    oh[2 * i]     = __halves2bfloat162(h[0], h[1]);
    oh[2 * i + 1] = __halves2bfloat162(h[2], h[3]);
    ol[2 * i]     = __halves2bfloat162(l[0], l[1]);
    ol[2 * i + 1] = __halves2bfloat162(l[2], l[3]);
}

__global__ __launch_bounds__(256) void prep_w(const float* __restrict__ Wq,
                                              const float* __restrict__ Wk,
                                              const float* __restrict__ Wv)
{
    const float* W = (blockIdx.z == 0) ? Wq : (blockIdx.z == 1) ? Wk : Wv;
    __shared__ float t[32][33];
    int tx = threadIdx.x, ty = threadIdx.y;        // 32 x 8
    int n0 = blockIdx.x * 32, k0 = blockIdx.y * 32;
    #pragma unroll
    for (int i = 0; i < 4; i++)
        t[ty + 8 * i][tx] = W[(size_t)(k0 + ty + 8 * i) * DM + n0 + tx];
    __syncthreads();
    __nv_bfloat16* oh = g_wth + (size_t)blockIdx.z * DM * DM;
    __nv_bfloat16* ol = g_wtl + (size_t)blockIdx.z * DM * DM;
    #pragma unroll
    for (int i = 0; i < 4; i++) {
        int n = n0 + ty + 8 * i;
        float v = t[tx][ty + 8 * i];
        __nv_bfloat16 h = __float2bfloat16(v);
        oh[(size_t)n * DM + k0 + tx] = h;
        ol[(size_t)n * DM + k0 + tx] = __float2bfloat16(v - __bfloat162float(h));
    }
}

// ---------------------------------------------------------------------------
// proj_mma: 128x128 tile, 3-pass bf16 hi/lo HMMA, cp.async 2-stage pipeline,
// ldmatrix fragment loads, 2 CTAs/SM. (unchanged — measured at 272us)
// ---------------------------------------------------------------------------
#define KC 32
#define NCHUNK (DM / KC)            // 32
#define SPAD 40                     // smem row stride in bf16 (80 B)
#define ARR_B (128 * SPAD * 2)      // 10240 bytes per array
#define STAGE_B (4 * ARR_B)         // 40960
#define PROJ_SMEM (2 * STAGE_B)     // 81920

__global__ __launch_bounds__(256, 2) void proj_mma(const float* __restrict__ bq,
                                                   const float* __restrict__ bk,
                                                   const float* __restrict__ bv)
{
    extern __shared__ char sm[];
    uint32_t smb = smem_u32(sm);

    int tid = threadIdx.x;
    int wid = tid >> 5, lane = tid & 31;
    int g = lane >> 2, tig = lane & 3;
    int l15 = lane & 15;
    int wm = wid >> 2, wn = wid & 3;             // 2 x 4 warp grid
    int n0 = blockIdx.x * 128;
    int m0 = blockIdx.y * 128;
    int mat = blockIdx.z;

    const float* bias = (mat == 0) ? bq : (mat == 1) ? bk : bv;
    __nv_bfloat16* outh = (mat == 0) ? g_qh : (mat == 1) ? g_kh : g_vh;
    __nv_bfloat16* outl = (mat == 0) ? g_ql : (mat == 1) ? g_kl : g_vl;
    const __nv_bfloat16* ah = g_xh + (size_t)m0 * DM;
    const __nv_bfloat16* al = g_xl + (size_t)m0 * DM;
    const __nv_bfloat16* bh = g_wth + (size_t)mat * DM * DM + (size_t)n0 * DM;
    const __nv_bfloat16* bl = g_wtl + (size_t)mat * DM * DM + (size_t)n0 * DM;

    float acc[4][4][4];
    #pragma unroll
    for (int i = 0; i < 4; i++)
        #pragma unroll
        for (int j = 0; j < 4; j++)
            #pragma unroll
            for (int r = 0; r < 4; r++) acc[i][j][r] = 0.f;

    int r0 = tid >> 2, c0 = (tid & 3) * 8;           // row, bf16-col
    uint32_t dOff0 = (uint32_t)(r0 * 80 + c0 * 2);
    uint32_t dOff1 = dOff0 + 64 * 80;
    const __nv_bfloat16* srcs[4] = {ah, al, bh, bl};

    uint32_t aOff = (uint32_t)(((wm * 64) + (lane & 7) + ((lane >> 3) & 1) * 8) * 80
                               + (lane >> 4) * 16);
    uint32_t bOff = (uint32_t)(((wn * 32) + (l15 & 7)) * 80 + (l15 >> 3) * 16);

    auto issue = [&](int c) {
        uint32_t sb = smb + (uint32_t)(c & 1) * STAGE_B;
        int k0 = c * KC;
        #pragma unroll
        for (int a = 0; a < 4; a++) {
            const __nv_bfloat16* s = srcs[a] + k0;
            uint32_t d = sb + (uint32_t)a * ARR_B;
            CP16(d + dOff0, s + (size_t)r0 * DM + c0);
            CP16(d + dOff1, s + (size_t)(r0 + 64) * DM + c0);
        }
        CP_COMMIT();
    };

    issue(0);

    #pragma unroll 1
    for (int c = 0; c < NCHUNK; c++) {
        if (c + 1 < NCHUNK) { issue(c + 1); CP_WAIT(1); }
        else                { CP_WAIT(0); }
        __syncthreads();

        uint32_t sb = smb + (uint32_t)(c & 1) * STAGE_B;
        uint32_t aH = sb + aOff;
        uint32_t aL = sb + ARR_B + aOff;
        uint32_t bH = sb + 2 * ARR_B + bOff;
        uint32_t bL = sb + 3 * ARR_B + bOff;

        #pragma unroll
        for (int kk = 0; kk < 2; kk++) {
            uint32_t kb = (uint32_t)kk * 32;   // 16 cols * 2B
            uint32_t vbh[4][2], vbl[4][2];
            #pragma unroll
            for (int nf = 0; nf < 4; nf++) {
                LDMX2(vbh[nf][0], vbh[nf][1], bH + (uint32_t)nf * 640 + kb);
                LDMX2(vbl[nf][0], vbl[nf][1], bL + (uint32_t)nf * 640 + kb);
            }
            #pragma unroll
            for (int mf = 0; mf < 4; mf++) {
                uint32_t a0, a1, a2, a3, b0, b1, b2, b3;
                LDMX4(a0, a1, a2, a3, aH + (uint32_t)mf * 1280 + kb);
                LDMX4(b0, b1, b2, b3, aL + (uint32_t)mf * 1280 + kb);
                #pragma unroll
                for (int nf = 0; nf < 4; nf++) {
                    MMA16816(acc[mf][nf], a0, a1, a2, a3, vbh[nf][0], vbh[nf][1]);
                    MMA16816(acc[mf][nf], a0, a1, a2, a3, vbl[nf][0], vbl[nf][1]);
                    MMA16816(acc[mf][nf], b0, b1, b2, b3, vbh[nf][0], vbh[nf][1]);
                }
            }
        }
        __syncthreads();
    }

    // Epilogue: bias + split to bf16 hi/lo + scatter to [b,h,t,d]
    #pragma unroll
    for (int mf = 0; mf < 4; mf++) {
        #pragma unroll
        for (int nf = 0; nf < 4; nf++) {
            int n = n0 + wn * 32 + nf * 8 + tig * 2;
            int h = n >> 6, d = n & 63;
            float b0 = bias[n], b1 = bias[n + 1];
            #pragma unroll
            for (int half = 0; half < 2; half++) {
                int m = m0 + wm * 64 + mf * 16 + g + half * 8;
                int b = m >> 10, t = m & 1023;
                size_t idx = (((size_t)b * HEADS + h) * T_LEN + t) * DH + d;
                float v0 = acc[mf][nf][half * 2] + b0;
                float v1 = acc[mf][nf][half * 2 + 1] + b1;
                __nv_bfloat16 h0 = __float2bfloat16(v0);
                __nv_bfloat16 h1 = __float2bfloat16(v1);
                *(uint32_t*)&outh[idx] = pack_bf16(h0, h1);
                *(uint32_t*)&outl[idx] = pack_f2bf(v0 - __bfloat162float(h0),
                                                   v1 - __bfloat162float(h1));
            }
        }
    }
}

// ---------------------------------------------------------------------------
// rel_mma: banded R[bh][t][c] = q[bh][t].Er[c] on HMMA (3-pass hi/lo).
// Er B-fragments via ldmatrix.x2. 128 thr, 64x64 tile. (unchanged)
// ---------------------------------------------------------------------------
#define EPAD 72
#define EROW (EPAD * 2)   // 144 bytes

__global__ __launch_bounds__(128) void rel_mma()
{
    __shared__ __nv_bfloat16 sEh[64][EPAD];
    __shared__ __nv_bfloat16 sEl[64][EPAD];

    int sb = blockIdx.x, tb = blockIdx.y, bh = blockIdx.z;
    if (tb + sb < 15) return;   // tile never read under causal mask

    int tid = threadIdx.x, w = tid >> 5, lane = tid & 31;
    int l15 = lane & 15;
    int t0 = tb * 64, s0 = sb * 64;

    const __nv_bfloat16* qh = g_qh + (size_t)bh * T_LEN * DH;
    const __nv_bfloat16* ql = g_ql + (size_t)bh * T_LEN * DH;

    for (int i = tid; i < 512; i += 128) {
        int r = i >> 3, c = (i & 7) * 8;
        *(uint4*)&sEh[r][c] = *(const uint4*)&g_erh[(s0 + r) * DH + c];
        *(uint4*)&sEl[r][c] = *(const uint4*)&g_erl[(s0 + r) * DH + c];
    }

    int rowA = t0 + w * 16 + (lane >> 2);
    int tig = lane & 3;
    uint32_t qfh[4][4], qfl[4][4];
    #pragma unroll
    for (int ks = 0; ks < 4; ks++) {
        int d0 = ks * 16 + tig * 2;
        qfh[ks][0] = *(const uint32_t*)&qh[(size_t)rowA * DH + d0];
        qfh[ks][1] = *(const uint32_t*)&qh[(size_t)(rowA + 8) * DH + d0];
        qfh[ks][2] = *(const uint32_t*)&qh[(size_t)rowA * DH + d0 + 8];
        qfh[ks][3] = *(const uint32_t*)&qh[(size_t)(rowA + 8) * DH + d0 + 8];
        qfl[ks][0] = *(const uint32_t*)&ql[(size_t)rowA * DH + d0];
        qfl[ks][1] = *(const uint32_t*)&ql[(size_t)(rowA + 8) * DH + d0];
        qfl[ks][2] = *(const uint32_t*)&ql[(size_t)rowA * DH + d0 + 8];
        qfl[ks][3] = *(const uint32_t*)&ql[(size_t)(rowA + 8) * DH + d0 + 8];
    }
    __syncthreads();

    float acc[8][4];
    #pragma unroll
    for (int f = 0; f < 8; f++)
        #pragma unroll
        for (int r = 0; r < 4; r++) acc[f][r] = 0.f;

    uint32_t eOff = (uint32_t)((l15 & 7) * EROW + (l15 >> 3) * 16);
    uint32_t eH = smem_u32(&sEh[0][0]) + eOff;
    uint32_t eL = smem_u32(&sEl[0][0]) + eOff;

    #pragma unroll
    for (int ks = 0; ks < 4; ks++) {
        uint32_t kb = (uint32_t)ks * 32;
        #pragma unroll
        for (int nf = 0; nf < 8; nf++) {
            uint32_t b0, b1, c0, c1;
            LDMX2(b0, b1, eH + (uint32_t)nf * 8 * EROW + kb);
            LDMX2(c0, c1, eL + (uint32_t)nf * 8 * EROW + kb);
            MMA16816(acc[nf], qfh[ks][0], qfh[ks][1], qfh[ks][2], qfh[ks][3], b0, b1);
            MMA16816(acc[nf], qfh[ks][0], qfh[ks][1], qfh[ks][2], qfh[ks][3], c0, c1);
            MMA16816(acc[nf], qfl[ks][0], qfl[ks][1], qfl[ks][2], qfl[ks][3], b0, b1);
        }
    }

    float* Rg = g_R + (size_t)bh * T_LEN * T_LEN;
    #pragma unroll
    for (int nf = 0; nf < 8; nf++) {
        int c = s0 + nf * 8 + tig * 2;
        *(float2*)&Rg[(size_t)rowA * T_LEN + c] = make_float2(acc[nf][0], acc[nf][1]);
        *(float2*)&Rg[(size_t)(rowA + 8) * T_LEN + c] = make_float2(acc[nf][2], acc[nf][3]);
    }
}

// ---------------------------------------------------------------------------
// attn_mma: FA2 flash attention on HMMA (3-pass hi/lo).
// 128-row t-tile, 256 threads (8 warps x 16 rows). cp.async double-buffered
// K/V tiles. K natural + ldmatrix, V natural + ldmatrix.trans.
// ---------------------------------------------------------------------------
#define ARR_AT (64 * EROW)          // 9216 B per array (64 rows x 144 B)
#define STAGE_AT (4 * ARR_AT)       // 36864
#define AT_SMEM (2 * STAGE_AT)      // 73728

__global__ __launch_bounds__(256, 1) void attn_mma(float* __restrict__ out)
{
    extern __shared__ char smA[];
    uint32_t smb = smem_u32(smA);

    int tid = threadIdx.x, w = tid >> 5, lane = tid & 31;
    int g = lane >> 2, tig = lane & 3;
    int l15 = lane & 15;
    int tb = blockIdx.x, bh = blockIdx.y;
    int t0 = tb * 128;

    const __nv_bfloat16* qh = g_qh + (size_t)bh * T_LEN * DH;
    const __nv_bfloat16* ql = g_ql + (size_t)bh * T_LEN * DH;
    const __nv_bfloat16* kh = g_kh + (size_t)bh * T_LEN * DH;
    const __nv_bfloat16* kl = g_kl + (size_t)bh * T_LEN * DH;
    const __nv_bfloat16* vh = g_vh + (size_t)bh * T_LEN * DH;
    const __nv_bfloat16* vl = g_vl + (size_t)bh * T_LEN * DH;
    const float* Rg = g_R + (size_t)bh * T_LEN * T_LEN;

    int rowA = t0 + w * 16 + g;          // warp w covers rows [t0+16w, t0+16w+16)
    int row1 = rowA + 8;

    // Q fragments (held for the whole kernel)
    uint32_t qfh[4][4], qfl[4][4];
    #pragma unroll
    for (int ks = 0; ks < 4; ks++) {
        int d0 = ks * 16 + tig * 2;
        qfh[ks][0] = *(const uint32_t*)&qh[(size_t)rowA * DH + d0];
        qfh[ks][1] = *(const uint32_t*)&qh[(size_t)row1 * DH + d0];
        qfh[ks][2] = *(const uint32_t*)&qh[(size_t)rowA * DH + d0 + 8];
        qfh[ks][3] = *(const uint32_t*)&qh[(size_t)row1 * DH + d0 + 8];
        qfl[ks][0] = *(const uint32_t*)&ql[(size_t)rowA * DH + d0];
        qfl[ks][1] = *(const uint32_t*)&ql[(size_t)row1 * DH + d0];
        qfl[ks][2] = *(const uint32_t*)&ql[(size_t)rowA * DH + d0 + 8];
        qfl[ks][3] = *(const uint32_t*)&ql[(size_t)row1 * DH + d0 + 8];
    }

    float m0 = -1e30f, m1 = -1e30f, l0 = 0.f, l1 = 0.f;
    float o[8][4];
    #pragma unroll
    for (int f = 0; f < 8; f++)
        #pragma unroll
        for (int r = 0; r < 4; r++) o[f][r] = 0.f;

    const float* R0 = Rg + (size_t)rowA * T_LEN + (T_LEN - 1 - rowA);
    const float* R1 = Rg + (size_t)row1 * T_LEN + (T_LEN - 1 - row1);

    // cp.async mapping: 256 threads cover 512 x 16B per array (64 rows x 128B)
    int cr0 = tid >> 3;                     // rows 0..31 (and +32)
    int cc0 = (tid & 7) * 8;                // bf16 col
    uint32_t cOff0 = (uint32_t)(cr0 * EROW + cc0 * 2);
    uint32_t cOff1 = cOff0 + 32 * EROW;
    const __nv_bfloat16* kvsrc[4] = {kh, kl, vh, vl};

    auto issueKV = [&](int sbt) {
        uint32_t st = smb + (uint32_t)(sbt & 1) * STAGE_AT;
        int s0 = sbt * 64;
        #pragma unroll
        for (int a = 0; a < 4; a++) {
            const __nv_bfloat16* s = kvsrc[a] + (size_t)s0 * DH;
            uint32_t d = st + (uint32_t)a * ARR_AT;
            CP16(d + cOff0, s + (size_t)cr0 * DH + cc0);
            CP16(d + cOff1, s + (size_t)(cr0 + 32) * DH + cc0);
        }
        CP_COMMIT();
    };

    // ldmatrix per-lane offsets (relative to array base)
    uint32_t kOff = (uint32_t)((l15 & 7) * EROW + (l15 >> 3) * 16);
    uint32_t vOff = (uint32_t)(((l15 & 7) + (l15 >> 3) * 8) * EROW);

    int sbMax = 2 * tb + 1;
    issueKV(0);

    #pragma unroll 1
    for (int sb = 0; sb <= sbMax; sb++) {
        int s0 = sb * 64;
        if (sb + 1 <= sbMax) { issueKV(sb + 1); CP_WAIT(1); }
        else                 { CP_WAIT(0); }
        __syncthreads();

        uint32_t st = smb + (uint32_t)(sb & 1) * STAGE_AT;
        uint32_t kBH = st + kOff;
        uint32_t kBL = st + ARR_AT + kOff;
        uint32_t vBH = st + 2 * ARR_AT + vOff;
        uint32_t vBL = st + 3 * ARR_AT + vOff;

        // S = Q @ K^T (3-pass)
        float s[8][4];
        #pragma unroll
        for (int f = 0; f < 8; f++)
            #pragma unroll
            for (int r = 0; r < 4; r++) s[f][r] = 0.f;

        #pragma unroll
        for (int ks = 0; ks < 4; ks++) {
            uint32_t kb = (uint32_t)ks * 32;
            #pragma unroll
            for (int nf = 0; nf < 8; nf++) {
                uint32_t b0, b1, c0, c1;
                LDMX2(b0, b1, kBH + (uint32_t)nf * 8 * EROW + kb);
                LDMX2(c0, c1, kBL + (uint32_t)nf * 8 * EROW + kb);
                MMA16816(s[nf], qfh[ks][0], qfh[ks][1], qfh[ks][2], qfh[ks][3], b0, b1);
                MMA16816(s[nf], qfh[ks][0], qfh[ks][1], qfh[ks][2], qfh[ks][3], c0, c1);
                MMA16816(s[nf], qfl[ks][0], qfl[ks][1], qfl[ks][2], qfl[ks][3], b0, b1);
            }
        }

        // rel add + scale + causal mask (clamped indices keep loads in-bounds)
        #pragma unroll
        for (int nf = 0; nf < 8; nf++) {
            int sc = s0 + nf * 8 + tig * 2;
            float r00 = R0[min(sc, rowA)];
            float r01 = R0[min(sc + 1, rowA)];
            float r10 = R1[min(sc, row1)];
            float r11 = R1[min(sc + 1, row1)];
            s[nf][0] = (sc     <= rowA) ? (s[nf][0] + r00) * 0.125f : -1e30f;
            s[nf][1] = (sc + 1 <= rowA) ? (s[nf][1] + r01) * 0.125f : -1e30f;
            s[nf][2] = (sc     <= row1) ? (s[nf][2] + r10) * 0.125f : -1e30f;
            s[nf][3] = (sc + 1 <= row1) ? (s[nf][3] + r11) * 0.125f : -1e30f;
        }

        // online softmax (rows rowA, row1); cols spread over quad (tig)
        float mx0 = -1e30f, mx1 = -1e30f;
        #pragma unroll
        for (int nf = 0; nf < 8; nf++) {
            mx0 = fmaxf(mx0, fmaxf(s[nf][0], s[nf][1]));
            mx1 = fmaxf(mx1, fmaxf(s[nf][2], s[nf][3]));
        }
        mx0 = fmaxf(mx0, __shfl_xor_sync(0xffffffffu, mx0, 1));
        mx0 = fmaxf(mx0, __shfl_xor_sync(0xffffffffu, mx0, 2));
        mx1 = fmaxf(mx1, __shfl_xor_sync(0xffffffffu, mx1, 1));
        mx1 = fmaxf(mx1, __shfl_xor_sync(0xffffffffu, mx1, 2));

        float mn0 = fmaxf(m0, mx0), a0 = __expf(m0 - mn0); m0 = mn0;
        float mn1 = fmaxf(m1, mx1), a1 = __expf(m1 - mn1); m1 = mn1;

        float rs0 = 0.f, rs1 = 0.f;
        #pragma unroll
        for (int nf = 0; nf < 8; nf++) {
            s[nf][0] = __expf(s[nf][0] - mn0);
            s[nf][1] = __expf(s[nf][1] - mn0);
            s[nf][2] = __expf(s[nf][2] - mn1);
            s[nf][3] = __expf(s[nf][3] - mn1);
            rs0 += s[nf][0] + s[nf][1];
            rs1 += s[nf][2] + s[nf][3];
        }
        rs0 += __shfl_xor_sync(0xffffffffu, rs0, 1);
        rs0 += __shfl_xor_sync(0xffffffffu, rs0, 2);
        rs1 += __shfl_xor_sync(0xffffffffu, rs1, 1);
        rs1 += __shfl_xor_sync(0xffffffffu, rs1, 2);
        l0 = l0 * a0 + rs0;
        l1 = l1 * a1 + rs1;
        #pragma unroll
        for (int f = 0; f < 8; f++) {
            o[f][0] *= a0; o[f][1] *= a0;
            o[f][2] *= a1; o[f][3] *= a1;
        }

        // P -> bf16 hi/lo A-fragments (register reuse: c0..c3 == a0..a3)
        uint32_t ph[8][2], pl[8][2];
        #pragma unroll
        for (int f = 0; f < 8; f++) {
            __nv_bfloat16 h00 = __float2bfloat16(s[f][0]);
            __nv_bfloat16 h01 = __float2bfloat16(s[f][1]);
            __nv_bfloat16 h10 = __float2bfloat16(s[f][2]);
            __nv_bfloat16 h11 = __float2bfloat16(s[f][3]);
            ph[f][0] = pack_bf16(h00, h01);
            ph[f][1] = pack_bf16(h10, h11);
            pl[f][0] = pack_f2bf(s[f][0] - __bfloat162float(h00),
                                 s[f][1] - __bfloat162float(h01));
            pl[f][1] = pack_f2bf(s[f][2] - __bfloat162float(h10),
                                 s[f][3] - __bfloat162float(h11));
        }

        // O += P @ V (3-pass); V B-frags via ldmatrix.trans from natural [s][d]
        #pragma unroll
        for (int j = 0; j < 4; j++) {
            uint32_t aH0 = ph[2 * j][0], aH1 = ph[2 * j][1];
            uint32_t aH2 = ph[2 * j + 1][0], aH3 = ph[2 * j + 1][1];
            uint32_t aL0 = pl[2 * j][0], aL1 = pl[2 * j][1];
            uint32_t aL2 = pl[2 * j + 1][0], aL3 = pl[2 * j + 1][1];
            uint32_t jrow = (uint32_t)(j * 16) * EROW;
            #pragma unroll
            for (int nf = 0; nf < 8; nf++) {
                uint32_t bH0, bH1, bL0, bL1;
                LDMX2T(bH0, bH1, vBH + jrow + (uint32_t)nf * 16);
                LDMX2T(bL0, bL1, vBL + jrow + (uint32_t)nf * 16);
                MMA16816(o[nf], aH0, aH1, aH2, aH3, bH0, bH1);
                MMA16816(o[nf], aH0, aH1, aH2, aH3, bL0, bL1);
                MMA16816(o[nf], aL0, aL1, aL2, aL3, bH0, bH1);
            }
        }
        __syncthreads();   // all reads of this stage done before issueKV reuses it
    }

    // epilogue: out[b][t][h*64+d]
    int b = bh >> 4, h = bh & 15;
    float i0 = 1.f / l0, i1 = 1.f / l1;
    #pragma unroll
    for (int nf = 0; nf < 8; nf++) {
        int d = nf * 8 + tig * 2;
        float* op0 = out + ((size_t)b * T_LEN + rowA) * DM + h * DH + d;
        float* op1 = out + ((size_t)b * T_LEN + row1) * DM + h * DH + d;
        *(float2*)op0 = make_float2(o[nf][0] * i0, o[nf][1] * i0);
        *(float2*)op1 = make_float2(o[nf][2] * i1, o[nf][3] * i1);
    }
}

// ---------------------------------------------------------------------------
extern "C" void kernel_launch(void* const* d_in, const int* in_sizes, int n_in,
                              void* d_out, int out_size)
{
    const float* x  = (const float*)d_in[0];
    const float* Wq = (const float*)d_in[1];
    const float* bq = (const float*)d_in[2];
    const float* Wk = (const float*)d_in[3];
    const float* bk = (const float*)d_in[4];
    const float* Wv = (const float*)d_in[5];
    const float* bv = (const float*)d_in[6];
    const float* Er = (const float*)d_in[7];
    float* out = (float*)d_out;

    int NB = in_sizes[0] / (T_LEN * DM);
    if (NB > NB_MAX) NB = NB_MAX;

    cudaFuncSetAttribute(proj_mma, cudaFuncAttributeMaxDynamicSharedMemorySize,
                         PROJ_SMEM);
    cudaFuncSetAttribute(attn_mma, cudaFuncAttributeMaxDynamicSharedMemorySize,
                         AT_SMEM);

    // 0) split x / Er, transpose+split W to bf16 hi/lo
    int n4 = NB * T_LEN * DM / 4;
    prep_x<<<(n4 + 255) / 256, 256>>>(x, n4);
    prep_er<<<(T_LEN * DH / 4 + 255) / 256, 256>>>(Er);
    prep_w<<<dim3(32, 32, 3), dim3(32, 8)>>>(Wq, Wk, Wv);

    // 1) q,k,v projections on HMMA (cp.async pipeline, ldmatrix)
    dim3 pgrid(8, NB * 8, 3);
    proj_mma<<<pgrid, 256, PROJ_SMEM>>>(bq, bk, bv);

    // 2) relative scores R = q @ Er^T (banded) on HMMA
    dim3 rgrid(16, 16, NB * HEADS);
    rel_mma<<<rgrid, 128>>>();

    // 3) flash attention on HMMA (128-row t-tiles, cp.async K/V pipeline)
    dim3 agrid(8, NB * HEADS);
    attn_mma<<<agrid, 256, AT_SMEM>>>(out);
}

// round 12
// speedup vs baseline: 2.3229x; 1.0008x over previous
#include <cuda_runtime.h>
#include <cuda_bf16.h>
#include <cstdint>

// Problem constants (fixed by the reference: N=4, T=1024, H=16, D_HEAD=64)
#define T_LEN 1024
#define HEADS 16
#define DH 64
#define NB_MAX 4
#define DM 1024

// ---------------------------------------------------------------------------
// Scratch (device globals — no allocation allowed in kernel_launch)
// ---------------------------------------------------------------------------
__device__ __align__(16) float g_R[(size_t)NB_MAX * HEADS * T_LEN * T_LEN]; // [bh][t][c], c=s-t+1023
__device__ __align__(16) __nv_bfloat16 g_xh[NB_MAX * T_LEN * DM];
__device__ __align__(16) __nv_bfloat16 g_xl[NB_MAX * T_LEN * DM];
__device__ __align__(16) __nv_bfloat16 g_wth[3 * DM * DM];  // W^T [mat][n][k]
__device__ __align__(16) __nv_bfloat16 g_wtl[3 * DM * DM];
__device__ __align__(16) __nv_bfloat16 g_qh[NB_MAX * HEADS * T_LEN * DH];
__device__ __align__(16) __nv_bfloat16 g_ql[NB_MAX * HEADS * T_LEN * DH];
__device__ __align__(16) __nv_bfloat16 g_kh[NB_MAX * HEADS * T_LEN * DH];
__device__ __align__(16) __nv_bfloat16 g_kl[NB_MAX * HEADS * T_LEN * DH];
__device__ __align__(16) __nv_bfloat16 g_vh[NB_MAX * HEADS * T_LEN * DH];
__device__ __align__(16) __nv_bfloat16 g_vl[NB_MAX * HEADS * T_LEN * DH];
__device__ __align__(16) __nv_bfloat16 g_erh[T_LEN * DH];
__device__ __align__(16) __nv_bfloat16 g_erl[T_LEN * DH];

// mma.sync m16n8k16 row.col f32.bf16.bf16.f32 (base PTX — works on sm_100)
#define MMA16816(d, a0, a1, a2, a3, b0, b1)                                   \
    asm volatile(                                                             \
        "mma.sync.aligned.m16n8k16.row.col.f32.bf16.bf16.f32 "                \
        "{%0,%1,%2,%3}, {%4,%5,%6,%7}, {%8,%9}, {%0,%1,%2,%3};"               \
        : "+f"((d)[0]), "+f"((d)[1]), "+f"((d)[2]), "+f"((d)[3])              \
        : "r"(a0), "r"(a1), "r"(a2), "r"(a3), "r"(b0), "r"(b1))

#define LDMX4(r0, r1, r2, r3, a)                                              \
    asm volatile("ldmatrix.sync.aligned.m8n8.x4.shared.b16 {%0,%1,%2,%3}, [%4];" \
                 : "=r"(r0), "=r"(r1), "=r"(r2), "=r"(r3) : "r"(a))
#define LDMX2(r0, r1, a)                                                      \
    asm volatile("ldmatrix.sync.aligned.m8n8.x2.shared.b16 {%0,%1}, [%2];"    \
                 : "=r"(r0), "=r"(r1) : "r"(a))
#define LDMX2T(r0, r1, a)                                                     \
    asm volatile("ldmatrix.sync.aligned.m8n8.x2.trans.shared.b16 {%0,%1}, [%2];" \
                 : "=r"(r0), "=r"(r1) : "r"(a))
#define CP16(dst_u32, src)                                                    \
    asm volatile("cp.async.cg.shared.global [%0], [%1], 16;"                  \
                 :: "r"(dst_u32), "l"(src))
#define CP_COMMIT() asm volatile("cp.async.commit_group;" ::: "memory")
#define CP_WAIT(n)  asm volatile("cp.async.wait_group %0;" :: "n"(n) : "memory")

__device__ __forceinline__ uint32_t smem_u32(const void* p) {
    uint32_t a;
    asm("{ .reg .u64 t; cvta.to.shared.u64 t, %1; cvt.u32.u64 %0, t; }"
        : "=r"(a) : "l"(p));
    return a;
}
__device__ __forceinline__ uint32_t pack_bf16(__nv_bfloat16 a, __nv_bfloat16 b) {
    __nv_bfloat162 t = __halves2bfloat162(a, b);
    return *(uint32_t*)&t;
}
__device__ __forceinline__ uint32_t pack_f2bf(float a, float b) {
    __nv_bfloat162 t = __floats2bfloat162_rn(a, b);
    return *(uint32_t*)&t;
}

// ---------------------------------------------------------------------------
// prep kernels: fp32 -> bf16 hi/lo splits (x, Er), W transpose+split
// ---------------------------------------------------------------------------
__global__ __launch_bounds__(256) void prep_x(const float* __restrict__ x, int n4)
{
    int i = blockIdx.x * 256 + threadIdx.x;
    if (i >= n4) return;
    float4 v = ((const float4*)x)[i];
    __nv_bfloat16 h[4], l[4];
    float f[4] = {v.x, v.y, v.z, v.w};
    #pragma unroll
    for (int j = 0; j < 4; j++) {
        h[j] = __float2bfloat16(f[j]);
        l[j] = __float2bfloat16(f[j] - __bfloat162float(h[j]));
    }
    __nv_bfloat162* oh = (__nv_bfloat162*)g_xh;
    __nv_bfloat162* ol = (__nv_bfloat162*)g_xl;
    oh[2 * i]     = __halves2bfloat162(h[0], h[1]);
    oh[2 * i + 1] = __halves2bfloat162(h[2], h[3]);
    ol[2 * i]     = __halves2bfloat162(l[0], l[1]);
    ol[2 * i + 1] = __halves2bfloat162(l[2], l[3]);
}

__global__ __launch_bounds__(256) void prep_er(const float* __restrict__ er)
{
    int i = blockIdx.x * 256 + threadIdx.x;
    if (i >= T_LEN * DH / 4) return;
    float4 v = ((const float4*)er)[i];
    float f[4] = {v.x, v.y, v.z, v.w};
    __nv_bfloat16 h[4], l[4];
    #pragma unroll
    for (int j = 0; j < 4; j++) {
        h[j] = __float2bfloat16(f[j]);
        l[j] = __float2bfloat16(f[j] - __bfloat162float(h[j]));
    }
    __nv_bfloat162* oh = (__nv_bfloat162*)g_erh;
    __nv_bfloat162* ol = (__nv_bfloat162*)g_erl;
    oh[2 * i]     = __halves2bfloat162(h[0], h[1]);
    oh[2 * i + 1] = __halves2bfloat162(h[2], h[3]);
    ol[2 * i]     = __halves2bfloat162(l[0], l[1]);
    ol[2 * i + 1] = __halves2bfloat162(l[2], l[3]);
}

__global__ __launch_bounds__(256) void prep_w(const float* __restrict__ Wq,
                                              const float* __restrict__ Wk,
                                              const float* __restrict__ Wv)
{
    const float* W = (blockIdx.z == 0) ? Wq : (blockIdx.z == 1) ? Wk : Wv;
    __shared__ float t[32][33];
    int tx = threadIdx.x, ty = threadIdx.y;        // 32 x 8
    int n0 = blockIdx.x * 32, k0 = blockIdx.y * 32;
    #pragma unroll
    for (int i = 0; i < 4; i++)
        t[ty + 8 * i][tx] = W[(size_t)(k0 + ty + 8 * i) * DM + n0 + tx];
    __syncthreads();
    __nv_bfloat16* oh = g_wth + (size_t)blockIdx.z * DM * DM;
    __nv_bfloat16* ol = g_wtl + (size_t)blockIdx.z * DM * DM;
    #pragma unroll
    for (int i = 0; i < 4; i++) {
        int n = n0 + ty + 8 * i;
        float v = t[tx][ty + 8 * i];
        __nv_bfloat16 h = __float2bfloat16(v);
        oh[(size_t)n * DM + k0 + tx] = h;
        ol[(size_t)n * DM + k0 + tx] = __float2bfloat16(v - __bfloat162float(h));
    }
}

// ---------------------------------------------------------------------------
// proj_mma: 128x128 tile, 3-pass bf16 hi/lo HMMA, cp.async 2-stage pipeline,
// ldmatrix fragment loads, 2 CTAs/SM. MMA loops pass-major (ILP across nf).
// ---------------------------------------------------------------------------
#define KC 32
#define NCHUNK (DM / KC)            // 32
#define SPAD 40                     // smem row stride in bf16 (80 B)
#define ARR_B (128 * SPAD * 2)      // 10240 bytes per array
#define STAGE_B (4 * ARR_B)         // 40960
#define PROJ_SMEM (2 * STAGE_B)     // 81920

__global__ __launch_bounds__(256, 2) void proj_mma(const float* __restrict__ bq,
                                                   const float* __restrict__ bk,
                                                   const float* __restrict__ bv)
{
    extern __shared__ char sm[];
    uint32_t smb = smem_u32(sm);

    int tid = threadIdx.x;
    int wid = tid >> 5, lane = tid & 31;
    int g = lane >> 2, tig = lane & 3;
    int l15 = lane & 15;
    int wm = wid >> 2, wn = wid & 3;             // 2 x 4 warp grid
    int n0 = blockIdx.x * 128;
    int m0 = blockIdx.y * 128;
    int mat = blockIdx.z;

    const float* bias = (mat == 0) ? bq : (mat == 1) ? bk : bv;
    __nv_bfloat16* outh = (mat == 0) ? g_qh : (mat == 1) ? g_kh : g_vh;
    __nv_bfloat16* outl = (mat == 0) ? g_ql : (mat == 1) ? g_kl : g_vl;
    const __nv_bfloat16* ah = g_xh + (size_t)m0 * DM;
    const __nv_bfloat16* al = g_xl + (size_t)m0 * DM;
    const __nv_bfloat16* bh = g_wth + (size_t)mat * DM * DM + (size_t)n0 * DM;
    const __nv_bfloat16* bl = g_wtl + (size_t)mat * DM * DM + (size_t)n0 * DM;

    float acc[4][4][4];
    #pragma unroll
    for (int i = 0; i < 4; i++)
        #pragma unroll
        for (int j = 0; j < 4; j++)
            #pragma unroll
            for (int r = 0; r < 4; r++) acc[i][j][r] = 0.f;

    int r0 = tid >> 2, c0 = (tid & 3) * 8;           // row, bf16-col
    uint32_t dOff0 = (uint32_t)(r0 * 80 + c0 * 2);
    uint32_t dOff1 = dOff0 + 64 * 80;
    const __nv_bfloat16* srcs[4] = {ah, al, bh, bl};

    uint32_t aOff = (uint32_t)(((wm * 64) + (lane & 7) + ((lane >> 3) & 1) * 8) * 80
                               + (lane >> 4) * 16);
    uint32_t bOff = (uint32_t)(((wn * 32) + (l15 & 7)) * 80 + (l15 >> 3) * 16);

    auto issue = [&](int c) {
        uint32_t sb = smb + (uint32_t)(c & 1) * STAGE_B;
        int k0 = c * KC;
        #pragma unroll
        for (int a = 0; a < 4; a++) {
            const __nv_bfloat16* s = srcs[a] + k0;
            uint32_t d = sb + (uint32_t)a * ARR_B;
            CP16(d + dOff0, s + (size_t)r0 * DM + c0);
            CP16(d + dOff1, s + (size_t)(r0 + 64) * DM + c0);
        }
        CP_COMMIT();
    };

    issue(0);

    #pragma unroll 1
    for (int c = 0; c < NCHUNK; c++) {
        if (c + 1 < NCHUNK) { issue(c + 1); CP_WAIT(1); }
        else                { CP_WAIT(0); }
        __syncthreads();

        uint32_t sb = smb + (uint32_t)(c & 1) * STAGE_B;
        uint32_t aH = sb + aOff;
        uint32_t aL = sb + ARR_B + aOff;
        uint32_t bH = sb + 2 * ARR_B + bOff;
        uint32_t bL = sb + 3 * ARR_B + bOff;

        #pragma unroll
        for (int kk = 0; kk < 2; kk++) {
            uint32_t kb = (uint32_t)kk * 32;   // 16 cols * 2B
            uint32_t vbh[4][2], vbl[4][2];
            #pragma unroll
            for (int nf = 0; nf < 4; nf++) {
                LDMX2(vbh[nf][0], vbh[nf][1], bH + (uint32_t)nf * 640 + kb);
                LDMX2(vbl[nf][0], vbl[nf][1], bL + (uint32_t)nf * 640 + kb);
            }
            #pragma unroll
            for (int mf = 0; mf < 4; mf++) {
                uint32_t a0, a1, a2, a3, b0, b1, b2, b3;
                LDMX4(a0, a1, a2, a3, aH + (uint32_t)mf * 1280 + kb);
                LDMX4(b0, b1, b2, b3, aL + (uint32_t)mf * 1280 + kb);
                // pass-major: 4 independent MMAs between accumulator reuses
                #pragma unroll
                for (int nf = 0; nf < 4; nf++)
                    MMA16816(acc[mf][nf], a0, a1, a2, a3, vbh[nf][0], vbh[nf][1]);
                #pragma unroll
                for (int nf = 0; nf < 4; nf++)
                    MMA16816(acc[mf][nf], a0, a1, a2, a3, vbl[nf][0], vbl[nf][1]);
                #pragma unroll
                for (int nf = 0; nf < 4; nf++)
                    MMA16816(acc[mf][nf], b0, b1, b2, b3, vbh[nf][0], vbh[nf][1]);
            }
        }
        __syncthreads();
    }

    // Epilogue: bias + split to bf16 hi/lo + scatter to [b,h,t,d]
    #pragma unroll
    for (int mf = 0; mf < 4; mf++) {
        #pragma unroll
        for (int nf = 0; nf < 4; nf++) {
            int n = n0 + wn * 32 + nf * 8 + tig * 2;
            int h = n >> 6, d = n & 63;
            float b0 = bias[n], b1 = bias[n + 1];
            #pragma unroll
            for (int half = 0; half < 2; half++) {
                int m = m0 + wm * 64 + mf * 16 + g + half * 8;
                int b = m >> 10, t = m & 1023;
                size_t idx = (((size_t)b * HEADS + h) * T_LEN + t) * DH + d;
                float v0 = acc[mf][nf][half * 2] + b0;
                float v1 = acc[mf][nf][half * 2 + 1] + b1;
                __nv_bfloat16 h0 = __float2bfloat16(v0);
                __nv_bfloat16 h1 = __float2bfloat16(v1);
                *(uint32_t*)&outh[idx] = pack_bf16(h0, h1);
                *(uint32_t*)&outl[idx] = pack_f2bf(v0 - __bfloat162float(h0),
                                                   v1 - __bfloat162float(h1));
            }
        }
    }
}

// ---------------------------------------------------------------------------
// rel_mma: banded R[bh][t][c] = q[bh][t].Er[c] on HMMA (3-pass hi/lo).
// Pass-major MMA ordering (8-way ILP). 128 thr, 64x64 tile.
// ---------------------------------------------------------------------------
#define EPAD 72
#define EROW (EPAD * 2)   // 144 bytes

__global__ __launch_bounds__(128) void rel_mma()
{
    __shared__ __nv_bfloat16 sEh[64][EPAD];
    __shared__ __nv_bfloat16 sEl[64][EPAD];

    int sb = blockIdx.x, tb = blockIdx.y, bh = blockIdx.z;
    if (tb + sb < 15) return;   // tile never read under causal mask

    int tid = threadIdx.x, w = tid >> 5, lane = tid & 31;
    int l15 = lane & 15;
    int t0 = tb * 64, s0 = sb * 64;

    const __nv_bfloat16* qh = g_qh + (size_t)bh * T_LEN * DH;
    const __nv_bfloat16* ql = g_ql + (size_t)bh * T_LEN * DH;

    for (int i = tid; i < 512; i += 128) {
        int r = i >> 3, c = (i & 7) * 8;
        *(uint4*)&sEh[r][c] = *(const uint4*)&g_erh[(s0 + r) * DH + c];
        *(uint4*)&sEl[r][c] = *(const uint4*)&g_erl[(s0 + r) * DH + c];
    }

    int rowA = t0 + w * 16 + (lane >> 2);
    int tig = lane & 3;
    uint32_t qfh[4][4], qfl[4][4];
    #pragma unroll
    for (int ks = 0; ks < 4; ks++) {
        int d0 = ks * 16 + tig * 2;
        qfh[ks][0] = *(const uint32_t*)&qh[(size_t)rowA * DH + d0];
        qfh[ks][1] = *(const uint32_t*)&qh[(size_t)(rowA + 8) * DH + d0];
        qfh[ks][2] = *(const uint32_t*)&qh[(size_t)rowA * DH + d0 + 8];
        qfh[ks][3] = *(const uint32_t*)&qh[(size_t)(rowA + 8) * DH + d0 + 8];
        qfl[ks][0] = *(const uint32_t*)&ql[(size_t)rowA * DH + d0];
        qfl[ks][1] = *(const uint32_t*)&ql[(size_t)(rowA + 8) * DH + d0];
        qfl[ks][2] = *(const uint32_t*)&ql[(size_t)rowA * DH + d0 + 8];
        qfl[ks][3] = *(const uint32_t*)&ql[(size_t)(rowA + 8) * DH + d0 + 8];
    }
    __syncthreads();

    float acc[8][4];
    #pragma unroll
    for (int f = 0; f < 8; f++)
        #pragma unroll
        for (int r = 0; r < 4; r++) acc[f][r] = 0.f;

    uint32_t eOff = (uint32_t)((l15 & 7) * EROW + (l15 >> 3) * 16);
    uint32_t eH = smem_u32(&sEh[0][0]) + eOff;
    uint32_t eL = smem_u32(&sEl[0][0]) + eOff;

    #pragma unroll
    for (int ks = 0; ks < 4; ks++) {
        uint32_t kb = (uint32_t)ks * 32;
        uint32_t ebh[8][2], ebl[8][2];
        #pragma unroll
        for (int nf = 0; nf < 8; nf++) {
            LDMX2(ebh[nf][0], ebh[nf][1], eH + (uint32_t)nf * 8 * EROW + kb);
            LDMX2(ebl[nf][0], ebl[nf][1], eL + (uint32_t)nf * 8 * EROW + kb);
        }
        #pragma unroll
        for (int nf = 0; nf < 8; nf++)
            MMA16816(acc[nf], qfh[ks][0], qfh[ks][1], qfh[ks][2], qfh[ks][3],
                     ebh[nf][0], ebh[nf][1]);
        #pragma unroll
        for (int nf = 0; nf < 8; nf++)
            MMA16816(acc[nf], qfh[ks][0], qfh[ks][1], qfh[ks][2], qfh[ks][3],
                     ebl[nf][0], ebl[nf][1]);
        #pragma unroll
        for (int nf = 0; nf < 8; nf++)
            MMA16816(acc[nf], qfl[ks][0], qfl[ks][1], qfl[ks][2], qfl[ks][3],
                     ebh[nf][0], ebh[nf][1]);
    }

    float* Rg = g_R + (size_t)bh * T_LEN * T_LEN;
    #pragma unroll
    for (int nf = 0; nf < 8; nf++) {
        int c = s0 + nf * 8 + tig * 2;
        *(float2*)&Rg[(size_t)rowA * T_LEN + c] = make_float2(acc[nf][0], acc[nf][1]);
        *(float2*)&Rg[(size_t)(rowA + 8) * T_LEN + c] = make_float2(acc[nf][2], acc[nf][3]);
    }
}

// ---------------------------------------------------------------------------
// attn_mma: FA2 flash attention on HMMA (3-pass hi/lo).
// 128-row t-tile, 256 threads. cp.async double-buffered K/V tiles.
// Pass-major MMA ordering (8-way ILP) in both S and PV loops.
// ---------------------------------------------------------------------------
#define ARR_AT (64 * EROW)          // 9216 B per array (64 rows x 144 B)
#define STAGE_AT (4 * ARR_AT)       // 36864
#define AT_SMEM (2 * STAGE_AT)      // 73728

__global__ __launch_bounds__(256, 1) void attn_mma(float* __restrict__ out)
{
    extern __shared__ char smA[];
    uint32_t smb = smem_u32(smA);

    int tid = threadIdx.x, w = tid >> 5, lane = tid & 31;
    int g = lane >> 2, tig = lane & 3;
    int l15 = lane & 15;
    int tb = blockIdx.x, bh = blockIdx.y;
    int t0 = tb * 128;

    const __nv_bfloat16* qh = g_qh + (size_t)bh * T_LEN * DH;
    const __nv_bfloat16* ql = g_ql + (size_t)bh * T_LEN * DH;
    const __nv_bfloat16* kh = g_kh + (size_t)bh * T_LEN * DH;
    const __nv_bfloat16* kl = g_kl + (size_t)bh * T_LEN * DH;
    const __nv_bfloat16* vh = g_vh + (size_t)bh * T_LEN * DH;
    const __nv_bfloat16* vl = g_vl + (size_t)bh * T_LEN * DH;
    const float* Rg = g_R + (size_t)bh * T_LEN * T_LEN;

    int rowA = t0 + w * 16 + g;          // warp w covers rows [t0+16w, t0+16w+16)
    int row1 = rowA + 8;

    // Q fragments (held for the whole kernel)
    uint32_t qfh[4][4], qfl[4][4];
    #pragma unroll
    for (int ks = 0; ks < 4; ks++) {
        int d0 = ks * 16 + tig * 2;
        qfh[ks][0] = *(const uint32_t*)&qh[(size_t)rowA * DH + d0];
        qfh[ks][1] = *(const uint32_t*)&qh[(size_t)row1 * DH + d0];
        qfh[ks][2] = *(const uint32_t*)&qh[(size_t)rowA * DH + d0 + 8];
        qfh[ks][3] = *(const uint32_t*)&qh[(size_t)row1 * DH + d0 + 8];
        qfl[ks][0] = *(const uint32_t*)&ql[(size_t)rowA * DH + d0];
        qfl[ks][1] = *(const uint32_t*)&ql[(size_t)row1 * DH + d0];
        qfl[ks][2] = *(const uint32_t*)&ql[(size_t)rowA * DH + d0 + 8];
        qfl[ks][3] = *(const uint32_t*)&ql[(size_t)row1 * DH + d0 + 8];
    }

    float m0 = -1e30f, m1 = -1e30f, l0 = 0.f, l1 = 0.f;
    float o[8][4];
    #pragma unroll
    for (int f = 0; f < 8; f++)
        #pragma unroll
        for (int r = 0; r < 4; r++) o[f][r] = 0.f;

    const float* R0 = Rg + (size_t)rowA * T_LEN + (T_LEN - 1 - rowA);
    const float* R1 = Rg + (size_t)row1 * T_LEN + (T_LEN - 1 - row1);

    // cp.async mapping: 256 threads cover 512 x 16B per array (64 rows x 128B)
    int cr0 = tid >> 3;                     // rows 0..31 (and +32)
    int cc0 = (tid & 7) * 8;                // bf16 col
    uint32_t cOff0 = (uint32_t)(cr0 * EROW + cc0 * 2);
    uint32_t cOff1 = cOff0 + 32 * EROW;
    const __nv_bfloat16* kvsrc[4] = {kh, kl, vh, vl};

    auto issueKV = [&](int sbt) {
        uint32_t st = smb + (uint32_t)(sbt & 1) * STAGE_AT;
        int s0 = sbt * 64;
        #pragma unroll
        for (int a = 0; a < 4; a++) {
            const __nv_bfloat16* s = kvsrc[a] + (size_t)s0 * DH;
            uint32_t d = st + (uint32_t)a * ARR_AT;
            CP16(d + cOff0, s + (size_t)cr0 * DH + cc0);
            CP16(d + cOff1, s + (size_t)(cr0 + 32) * DH + cc0);
        }
        CP_COMMIT();
    };

    // ldmatrix per-lane offsets (relative to array base)
    uint32_t kOff = (uint32_t)((l15 & 7) * EROW + (l15 >> 3) * 16);
    uint32_t vOff = (uint32_t)(((l15 & 7) + (l15 >> 3) * 8) * EROW);

    int sbMax = 2 * tb + 1;
    issueKV(0);

    #pragma unroll 1
    for (int sb = 0; sb <= sbMax; sb++) {
        int s0 = sb * 64;
        if (sb + 1 <= sbMax) { issueKV(sb + 1); CP_WAIT(1); }
        else                 { CP_WAIT(0); }
        __syncthreads();

        uint32_t st = smb + (uint32_t)(sb & 1) * STAGE_AT;
        uint32_t kBH = st + kOff;
        uint32_t kBL = st + ARR_AT + kOff;
        uint32_t vBH = st + 2 * ARR_AT + vOff;
        uint32_t vBL = st + 3 * ARR_AT + vOff;

        // S = Q @ K^T (3-pass, pass-major)
        float s[8][4];
        #pragma unroll
        for (int f = 0; f < 8; f++)
            #pragma unroll
            for (int r = 0; r < 4; r++) s[f][r] = 0.f;

        #pragma unroll
        for (int ks = 0; ks < 4; ks++) {
            uint32_t kb = (uint32_t)ks * 32;
            uint32_t kbh[8][2], kbl[8][2];
            #pragma unroll
            for (int nf = 0; nf < 8; nf++) {
                LDMX2(kbh[nf][0], kbh[nf][1], kBH + (uint32_t)nf * 8 * EROW + kb);
                LDMX2(kbl[nf][0], kbl[nf][1], kBL + (uint32_t)nf * 8 * EROW + kb);
            }
            #pragma unroll
            for (int nf = 0; nf < 8; nf++)
                MMA16816(s[nf], qfh[ks][0], qfh[ks][1], qfh[ks][2], qfh[ks][3],
                         kbh[nf][0], kbh[nf][1]);
            #pragma unroll
            for (int nf = 0; nf < 8; nf++)
                MMA16816(s[nf], qfh[ks][0], qfh[ks][1], qfh[ks][2], qfh[ks][3],
                         kbl[nf][0], kbl[nf][1]);
            #pragma unroll
            for (int nf = 0; nf < 8; nf++)
                MMA16816(s[nf], qfl[ks][0], qfl[ks][1], qfl[ks][2], qfl[ks][3],
                         kbh[nf][0], kbh[nf][1]);
        }

        // rel add + scale + causal mask (clamped indices keep loads in-bounds)
        #pragma unroll
        for (int nf = 0; nf < 8; nf++) {
            int sc = s0 + nf * 8 + tig * 2;
            float r00 = R0[min(sc, rowA)];
            float r01 = R0[min(sc + 1, rowA)];
            float r10 = R1[min(sc, row1)];
            float r11 = R1[min(sc + 1, row1)];
            s[nf][0] = (sc     <= rowA) ? (s[nf][0] + r00) * 0.125f : -1e30f;
            s[nf][1] = (sc + 1 <= rowA) ? (s[nf][1] + r01) * 0.125f : -1e30f;
            s[nf][2] = (sc     <= row1) ? (s[nf][2] + r10) * 0.125f : -1e30f;
            s[nf][3] = (sc + 1 <= row1) ? (s[nf][3] + r11) * 0.125f : -1e30f;
        }

        // online softmax (rows rowA, row1); cols spread over quad (tig)
        float mx0 = -1e30f, mx1 = -1e30f;
        #pragma unroll
        for (int nf = 0; nf < 8; nf++) {
            mx0 = fmaxf(mx0, fmaxf(s[nf][0], s[nf][1]));
            mx1 = fmaxf(mx1, fmaxf(s[nf][2], s[nf][3]));
        }
        mx0 = fmaxf(mx0, __shfl_xor_sync(0xffffffffu, mx0, 1));
        mx0 = fmaxf(mx0, __shfl_xor_sync(0xffffffffu, mx0, 2));
        mx1 = fmaxf(mx1, __shfl_xor_sync(0xffffffffu, mx1, 1));
        mx1 = fmaxf(mx1, __shfl_xor_sync(0xffffffffu, mx1, 2));

        float mn0 = fmaxf(m0, mx0), a0 = __expf(m0 - mn0); m0 = mn0;
        float mn1 = fmaxf(m1, mx1), a1 = __expf(m1 - mn1); m1 = mn1;

        float rs0 = 0.f, rs1 = 0.f;
        #pragma unroll
        for (int nf = 0; nf < 8; nf++) {
            s[nf][0] = __expf(s[nf][0] - mn0);
            s[nf][1] = __expf(s[nf][1] - mn0);
            s[nf][2] = __expf(s[nf][2] - mn1);
            s[nf][3] = __expf(s[nf][3] - mn1);
            rs0 += s[nf][0] + s[nf][1];
            rs1 += s[nf][2] + s[nf][3];
        }
        rs0 += __shfl_xor_sync(0xffffffffu, rs0, 1);
        rs0 += __shfl_xor_sync(0xffffffffu, rs0, 2);
        rs1 += __shfl_xor_sync(0xffffffffu, rs1, 1);
        rs1 += __shfl_xor_sync(0xffffffffu, rs1, 2);
        l0 = l0 * a0 + rs0;
        l1 = l1 * a1 + rs1;
        #pragma unroll
        for (int f = 0; f < 8; f++) {
            o[f][0] *= a0; o[f][1] *= a0;
            o[f][2] *= a1; o[f][3] *= a1;
        }

        // P -> bf16 hi/lo A-fragments (register reuse: c0..c3 == a0..a3)
        uint32_t ph[8][2], pl[8][2];
        #pragma unroll
        for (int f = 0; f < 8; f++) {
            __nv_bfloat16 h00 = __float2bfloat16(s[f][0]);
            __nv_bfloat16 h01 = __float2bfloat16(s[f][1]);
            __nv_bfloat16 h10 = __float2bfloat16(s[f][2]);
            __nv_bfloat16 h11 = __float2bfloat16(s[f][3]);
            ph[f][0] = pack_bf16(h00, h01);
            ph[f][1] = pack_bf16(h10, h11);
            pl[f][0] = pack_f2bf(s[f][0] - __bfloat162float(h00),
                                 s[f][1] - __bfloat162float(h01));
            pl[f][1] = pack_f2bf(s[f][2] - __bfloat162float(h10),
                                 s[f][3] - __bfloat162float(h11));
        }

        // O += P @ V (3-pass, pass-major); V B-frags via ldmatrix.trans
        #pragma unroll
        for (int j = 0; j < 4; j++) {
            uint32_t aH0 = ph[2 * j][0], aH1 = ph[2 * j][1];
            uint32_t aH2 = ph[2 * j + 1][0], aH3 = ph[2 * j + 1][1];
            uint32_t aL0 = pl[2 * j][0], aL1 = pl[2 * j][1];
            uint32_t aL2 = pl[2 * j + 1][0], aL3 = pl[2 * j + 1][1];
            uint32_t jrow = (uint32_t)(j * 16) * EROW;
            uint32_t vbh[8][2], vbl[8][2];
            #pragma unroll
            for (int nf = 0; nf < 8; nf++) {
                LDMX2T(vbh[nf][0], vbh[nf][1], vBH + jrow + (uint32_t)nf * 16);
                LDMX2T(vbl[nf][0], vbl[nf][1], vBL + jrow + (uint32_t)nf * 16);
            }
            #pragma unroll
            for (int nf = 0; nf < 8; nf++)
                MMA16816(o[nf], aH0, aH1, aH2, aH3, vbh[nf][0], vbh[nf][1]);
            #pragma unroll
            for (int nf = 0; nf < 8; nf++)
                MMA16816(o[nf], aH0, aH1, aH2, aH3, vbl[nf][0], vbl[nf][1]);
            #pragma unroll
            for (int nf = 0; nf < 8; nf++)
                MMA16816(o[nf], aL0, aL1, aL2, aL3, vbh[nf][0], vbh[nf][1]);
        }
        __syncthreads();   // all reads of this stage done before issueKV reuses it
    }

    // epilogue: out[b][t][h*64+d]
    int b = bh >> 4, h = bh & 15;
    float i0 = 1.f / l0, i1 = 1.f / l1;
    #pragma unroll
    for (int nf = 0; nf < 8; nf++) {
        int d = nf * 8 + tig * 2;
        float* op0 = out + ((size_t)b * T_LEN + rowA) * DM + h * DH + d;
        float* op1 = out + ((size_t)b * T_LEN + row1) * DM + h * DH + d;
        *(float2*)op0 = make_float2(o[nf][0] * i0, o[nf][1] * i0);
        *(float2*)op1 = make_float2(o[nf][2] * i1, o[nf][3] * i1);
    }
}

// ---------------------------------------------------------------------------
extern "C" void kernel_launch(void* const* d_in, const int* in_sizes, int n_in,
                              void* d_out, int out_size)
{
    const float* x  = (const float*)d_in[0];
    const float* Wq = (const float*)d_in[1];
    const float* bq = (const float*)d_in[2];
    const float* Wk = (const float*)d_in[3];
    const float* bk = (const float*)d_in[4];
    const float* Wv = (const float*)d_in[5];
    const float* bv = (const float*)d_in[6];
    const float* Er = (const float*)d_in[7];
    float* out = (float*)d_out;

    int NB = in_sizes[0] / (T_LEN * DM);
    if (NB > NB_MAX) NB = NB_MAX;

    cudaFuncSetAttribute(proj_mma, cudaFuncAttributeMaxDynamicSharedMemorySize,
                         PROJ_SMEM);
    cudaFuncSetAttribute(attn_mma, cudaFuncAttributeMaxDynamicSharedMemorySize,
                         AT_SMEM);

    // 0) split x / Er, transpose+split W to bf16 hi/lo
    int n4 = NB * T_LEN * DM / 4;
    prep_x<<<(n4 + 255) / 256, 256>>>(x, n4);
    prep_er<<<(T_LEN * DH / 4 + 255) / 256, 256>>>(Er);
    prep_w<<<dim3(32, 32, 3), dim3(32, 8)>>>(Wq, Wk, Wv);

    // 1) q,k,v projections on HMMA (cp.async pipeline, ldmatrix, pass-major)
    dim3 pgrid(8, NB * 8, 3);
    proj_mma<<<pgrid, 256, PROJ_SMEM>>>(bq, bk, bv);

    // 2) relative scores R = q @ Er^T (banded) on HMMA
    dim3 rgrid(16, 16, NB * HEADS);
    rel_mma<<<rgrid, 128>>>();

    // 3) flash attention on HMMA (128-row t-tiles, cp.async K/V pipeline)
    dim3 agrid(8, NB * HEADS);
    attn_mma<<<agrid, 256, AT_SMEM>>>(out);
}